// round 4
// baseline (speedup 1.0000x reference)
#include <cuda_runtime.h>

// Problem constants (fixed shapes per reference)
#define NSRC  10000
#define NDST  10000
#define NTOT  20000
#define INS   512
#define IND   256
#define HIDD  512
#define OUTD  256
#define NEDGE 160000
#define EPSB  1e-5f

// ---------------------------------------------------------------------------
// Scratch (static __device__ — no allocations allowed)
// ---------------------------------------------------------------------------
__device__ float g_X [NTOT * HIDD];   // concat(h_src, h_dst)
__device__ float g_Z1[NSRC * HIDD];   // X[:10k] @ W1l.T  (pre-transformed messages L1)
__device__ float g_T1[NTOT * HIDD];   // layer-1 pre-BN / post-BN activations
__device__ float g_Z2[NSRC * OUTD];   // Y[:10k]  @ W2l.T (pre-transformed messages L2)
__device__ int   g_edges[2 * NEDGE];  // canonical int32 edge list (src | dst)
__device__ int   g_is64;
__device__ int   g_cnt[NDST];
__device__ int   g_off[NDST];
__device__ int   g_cur[NDST];
__device__ int   g_csr[NEDGE];
__device__ float g_colsum[HIDD];
__device__ float g_colsumsq[HIDD];
__device__ float g_sc[HIDD];
__device__ float g_sh[HIDD];

// ---------------------------------------------------------------------------
// Edge dtype detection + canonicalization.
// JAX with x64 disabled silently stores edge_index as int32 even after
// .astype(jnp.int64); handle both. For little-endian int64 values < 2^31,
// every odd int32 word is 0. For genuine int32 src indices (random in
// [0,10000)), 32 consecutive odd words all being zero is ~impossible.
// ---------------------------------------------------------------------------
__global__ void k_detect(const void* p) {
    const int* q = (const int*)p;
    int all0 = 1;
    for (int i = 1; i < 64; i += 2)
        if (q[i] != 0) all0 = 0;
    g_is64 = all0;
}

__global__ void k_convert(const void* p) {
    int i = blockIdx.x * blockDim.x + threadIdx.x;
    if (i < 2 * NEDGE) {
        int v;
        if (g_is64) v = (int)((const long long*)p)[i];
        else        v = ((const int*)p)[i];
        g_edges[i] = v;
    }
}

// ---------------------------------------------------------------------------
// Graph preprocessing: histogram -> scan -> CSR fill
// ---------------------------------------------------------------------------
__global__ void k_zero() {
    int i = blockIdx.x * blockDim.x + threadIdx.x;
    if (i < NDST) g_cnt[i] = 0;
    if (i < HIDD) { g_colsum[i] = 0.f; g_colsumsq[i] = 0.f; }
}

__global__ void k_hist() {
    int i = blockIdx.x * blockDim.x + threadIdx.x;
    if (i < NEDGE) {
        unsigned d = (unsigned)(g_edges[NEDGE + i] - NSRC);
        if (d < NDST) atomicAdd(&g_cnt[d], 1);
    }
}

__global__ void k_scan() {
    // single block, 1024 threads, 10 items each (10240 >= 10000)
    __shared__ int part[1024];
    const int PER = 10;
    int t = threadIdx.x;
    int base = t * PER;
    int loc[PER];
    int s = 0;
#pragma unroll
    for (int i = 0; i < PER; i++) {
        int idx = base + i;
        int v = (idx < NDST) ? g_cnt[idx] : 0;
        loc[i] = s; s += v;
    }
    part[t] = s;
    __syncthreads();
    for (int d = 1; d < 1024; d <<= 1) {
        int v = (t >= d) ? part[t - d] : 0;
        __syncthreads();
        part[t] += v;
        __syncthreads();
    }
    int ex = (t == 0) ? 0 : part[t - 1];
#pragma unroll
    for (int i = 0; i < PER; i++) {
        int idx = base + i;
        if (idx < NDST) { int o = ex + loc[i]; g_off[idx] = o; g_cur[idx] = o; }
    }
}

__global__ void k_fill() {
    int i = blockIdx.x * blockDim.x + threadIdx.x;
    if (i < NEDGE) {
        unsigned d = (unsigned)(g_edges[NEDGE + i] - NSRC);
        unsigned s = (unsigned)g_edges[i];
        if (d < NDST && s < NSRC) {
            int p = atomicAdd(&g_cur[d], 1);
            if (p < NEDGE) g_csr[p] = (int)s;
        }
    }
}

// ---------------------------------------------------------------------------
// GEMM:  C[M,N] = A[M,K] @ W[N,K]^T (+ bias[n])
// 128x128x16 tile, 256 threads, 8x8 per thread, packed fma.rn.f32x2
// ---------------------------------------------------------------------------
#define BM 128
#define BN 128
#define BKK 16

__global__ void __launch_bounds__(256) k_gemm(
    const float* __restrict__ A, const float* __restrict__ W,
    const float* __restrict__ bias, float* __restrict__ C,
    int M, int N, int K)
{
    __shared__ __align__(16) float As[BKK][BM + 4];
    __shared__ __align__(16) float Bs[BKK][BN + 4];

    int tid = threadIdx.x;
    int tx = tid & 15;        // 0..15 -> n fragment
    int ty = tid >> 4;        // 0..15 -> m fragment
    int m0 = blockIdx.y * BM;
    int n0 = blockIdx.x * BN;

    unsigned long long acc[8][4];
#pragma unroll
    for (int i = 0; i < 8; i++)
#pragma unroll
        for (int j = 0; j < 4; j++) acc[i][j] = 0ull;  // {0.f, 0.f}

    for (int k0 = 0; k0 < K; k0 += BKK) {
        // --- load A tile (transposed into As[k][m]) ---
#pragma unroll
        for (int l = 0; l < 2; l++) {
            int f  = tid + l * 256;        // float4 id within 128x16 tile
            int m  = f >> 2;
            int kq = (f & 3) << 2;
            int gm = m0 + m;
            float4 v = make_float4(0.f, 0.f, 0.f, 0.f);
            if (gm < M) v = *(const float4*)(A + (size_t)gm * K + (k0 + kq));
            As[kq + 0][m] = v.x; As[kq + 1][m] = v.y;
            As[kq + 2][m] = v.z; As[kq + 3][m] = v.w;
        }
        // --- load W tile (N is always a multiple of 128 here) ---
#pragma unroll
        for (int l = 0; l < 2; l++) {
            int f  = tid + l * 256;
            int n  = f >> 2;
            int kq = (f & 3) << 2;
            float4 v = *(const float4*)(W + (size_t)(n0 + n) * K + (k0 + kq));
            Bs[kq + 0][n] = v.x; Bs[kq + 1][n] = v.y;
            Bs[kq + 2][n] = v.z; Bs[kq + 3][n] = v.w;
        }
        __syncthreads();

#pragma unroll
        for (int k = 0; k < BKK; k++) {
            float4 alo = *(const float4*)&As[k][ty * 8];
            float4 ahi = *(const float4*)&As[k][ty * 8 + 4];
            ulonglong2 bA = *(const ulonglong2*)&Bs[k][tx * 8];
            ulonglong2 bB = *(const ulonglong2*)&Bs[k][tx * 8 + 4];
            unsigned long long b0 = bA.x, b1 = bA.y, b2 = bB.x, b3 = bB.y;
            float av[8] = {alo.x, alo.y, alo.z, alo.w, ahi.x, ahi.y, ahi.z, ahi.w};
#pragma unroll
            for (int i = 0; i < 8; i++) {
                unsigned long long ad;
                asm("mov.b64 %0, {%1, %1};" : "=l"(ad) : "f"(av[i]));
                asm("fma.rn.f32x2 %0, %1, %2, %0;" : "+l"(acc[i][0]) : "l"(ad), "l"(b0));
                asm("fma.rn.f32x2 %0, %1, %2, %0;" : "+l"(acc[i][1]) : "l"(ad), "l"(b1));
                asm("fma.rn.f32x2 %0, %1, %2, %0;" : "+l"(acc[i][2]) : "l"(ad), "l"(b2));
                asm("fma.rn.f32x2 %0, %1, %2, %0;" : "+l"(acc[i][3]) : "l"(ad), "l"(b3));
            }
        }
        __syncthreads();
    }

    // --- epilogue ---
#pragma unroll
    for (int i = 0; i < 8; i++) {
        int gm = m0 + ty * 8 + i;
        if (gm < M) {
            float* crow = C + (size_t)gm * N + n0 + tx * 8;
#pragma unroll
            for (int j = 0; j < 4; j++) {
                float lo, hi;
                asm("mov.b64 {%0, %1}, %2;" : "=f"(lo), "=f"(hi) : "l"(acc[i][j]));
                int n = n0 + tx * 8 + 2 * j;
                if (bias) { lo += bias[n]; hi += bias[n + 1]; }
                crow[2 * j]     = lo;
                crow[2 * j + 1] = hi;
            }
        }
    }
}

// ---------------------------------------------------------------------------
// CSR aggregation: C[d] += mean_{s in nbrs(d)} Z[s]    (row width = blockDim*4)
// one block per dst node; atomics-free, loads hit L2 (Z fits in 126MB L2)
// ---------------------------------------------------------------------------
__global__ void k_agg(const float* __restrict__ Z, float* __restrict__ C) {
    int d   = blockIdx.x;
    int deg = g_cnt[d];
    if (deg == 0) return;                       // max(cnt,1): mean is exactly 0
    int W4  = blockDim.x;                       // row width in float4
    const float4* Z4 = (const float4*)Z;
    float4 acc = make_float4(0.f, 0.f, 0.f, 0.f);
    int o = g_off[d];
    for (int e = 0; e < deg; e++) {
        int s = g_csr[o + e];
        float4 v = Z4[(size_t)s * W4 + threadIdx.x];
        acc.x += v.x; acc.y += v.y; acc.z += v.z; acc.w += v.w;
    }
    float inv = 1.0f / (float)deg;
    float4* C4 = (float4*)C;
    size_t oi = (size_t)d * W4 + threadIdx.x;
    float4 c = C4[oi];
    c.x += acc.x * inv; c.y += acc.y * inv;
    c.z += acc.z * inv; c.w += acc.w * inv;
    C4[oi] = c;
}

// ---------------------------------------------------------------------------
// BatchNorm (training stats, biased var) + ReLU
// ---------------------------------------------------------------------------
__global__ void k_bnstats(const float* __restrict__ T) {
    // 128 threads: each owns 4 consecutive columns (one float4)
    const float4* T4 = (const float4*)T;
    float4 s = make_float4(0.f, 0.f, 0.f, 0.f);
    float4 q = make_float4(0.f, 0.f, 0.f, 0.f);
    for (int r = blockIdx.x; r < NTOT; r += gridDim.x) {
        float4 v = T4[(size_t)r * (HIDD / 4) + threadIdx.x];
        s.x += v.x; s.y += v.y; s.z += v.z; s.w += v.w;
        q.x += v.x * v.x; q.y += v.y * v.y; q.z += v.z * v.z; q.w += v.w * v.w;
    }
    int c = threadIdx.x * 4;
    atomicAdd(&g_colsum[c + 0], s.x); atomicAdd(&g_colsum[c + 1], s.y);
    atomicAdd(&g_colsum[c + 2], s.z); atomicAdd(&g_colsum[c + 3], s.w);
    atomicAdd(&g_colsumsq[c + 0], q.x); atomicAdd(&g_colsumsq[c + 1], q.y);
    atomicAdd(&g_colsumsq[c + 2], q.z); atomicAdd(&g_colsumsq[c + 3], q.w);
}

__global__ void k_bncoef(const float* __restrict__ gamma,
                         const float* __restrict__ beta) {
    int c = threadIdx.x;
    if (c < HIDD) {
        float mu  = g_colsum[c]   * (1.0f / NTOT);
        float var = g_colsumsq[c] * (1.0f / NTOT) - mu * mu;
        float s = gamma[c] * rsqrtf(var + EPSB);
        g_sc[c] = s;
        g_sh[c] = beta[c] - mu * s;
    }
}

__global__ void k_bnapply(float* __restrict__ T) {
    int idx = blockIdx.x * blockDim.x + threadIdx.x;          // float4 index
    const int TOT4 = NTOT * (HIDD / 4);
    if (idx >= TOT4) return;
    int c4 = idx & (HIDD / 4 - 1);
    float4 v = ((float4*)T)[idx];
    float4 s = ((const float4*)g_sc)[c4];
    float4 h = ((const float4*)g_sh)[c4];
    v.x = fmaxf(fmaf(v.x, s.x, h.x), 0.f);
    v.y = fmaxf(fmaf(v.y, s.y, h.y), 0.f);
    v.z = fmaxf(fmaf(v.z, s.z, h.z), 0.f);
    v.w = fmaxf(fmaf(v.w, s.w, h.w), 0.f);
    ((float4*)T)[idx] = v;
}

// ---------------------------------------------------------------------------
// Launch
// ---------------------------------------------------------------------------
extern "C" void kernel_launch(void* const* d_in, const int* in_sizes, int n_in,
                              void* d_out, int out_size) {
    const float* x_src = (const float*)d_in[0];
    const float* x_dst = (const float*)d_in[1];
    const float* W_src = (const float*)d_in[2];
    const float* b_src = (const float*)d_in[3];
    const float* W_dst = (const float*)d_in[4];
    const float* b_dst = (const float*)d_in[5];
    const float* W1l   = (const float*)d_in[6];
    const float* b1    = (const float*)d_in[7];
    const float* W1r   = (const float*)d_in[8];
    const float* W2l   = (const float*)d_in[9];
    const float* b2    = (const float*)d_in[10];
    const float* W2r   = (const float*)d_in[11];
    const float* gamma = (const float*)d_in[12];
    const float* beta  = (const float*)d_in[13];
    const void*  ei    = d_in[14];
    float* out = (float*)d_out;

    float *Xp, *Z1p, *T1p, *Z2p;
    cudaGetSymbolAddress((void**)&Xp,  g_X);
    cudaGetSymbolAddress((void**)&Z1p, g_Z1);
    cudaGetSymbolAddress((void**)&T1p, g_T1);
    cudaGetSymbolAddress((void**)&Z2p, g_Z2);

    // canonicalize edge list dtype (int32 vs int64), then preprocess graph
    k_detect<<<1, 1>>>(ei);
    k_convert<<<(2 * NEDGE + 255) / 256, 256>>>(ei);
    k_zero<<<(NDST + 255) / 256, 256>>>();
    k_hist<<<(NEDGE + 255) / 256, 256>>>();
    k_scan<<<1, 1024>>>();
    k_fill<<<(NEDGE + 255) / 256, 256>>>();

    // input projections -> X = concat(h_src, h_dst)
    k_gemm<<<dim3(HIDD / BN, (NSRC + BM - 1) / BM), 256>>>(
        x_src, W_src, b_src, Xp, NSRC, HIDD, INS);
    k_gemm<<<dim3(HIDD / BN, (NDST + BM - 1) / BM), 256>>>(
        x_dst, W_dst, b_dst, Xp + (size_t)NSRC * HIDD, NDST, HIDD, IND);

    // layer 1: Z1 = X[:10k] @ W1l.T ; T1 = X @ W1r.T + b1 ; T1[dst] += mean(Z1[src])
    k_gemm<<<dim3(HIDD / BN, (NSRC + BM - 1) / BM), 256>>>(
        Xp, W1l, nullptr, Z1p, NSRC, HIDD, HIDD);
    k_gemm<<<dim3(HIDD / BN, (NTOT + BM - 1) / BM), 256>>>(
        Xp, W1r, b1, T1p, NTOT, HIDD, HIDD);
    k_agg<<<NDST, HIDD / 4>>>(Z1p, T1p + (size_t)NSRC * HIDD);

    // BatchNorm + ReLU (in place on T1)
    k_bnstats<<<256, HIDD / 4>>>(T1p);
    k_bncoef<<<1, HIDD>>>(gamma, beta);
    k_bnapply<<<(NTOT * (HIDD / 4) + 255) / 256, 256>>>(T1p);

    // layer 2: Z2 = Y[:10k] @ W2l.T ; OUT = Y @ W2r.T + b2 ; OUT[dst] += mean(Z2[src])
    k_gemm<<<dim3(OUTD / BN, (NSRC + BM - 1) / BM), 256>>>(
        T1p, W2l, nullptr, Z2p, NSRC, OUTD, HIDD);
    k_gemm<<<dim3(OUTD / BN, (NTOT + BM - 1) / BM), 256>>>(
        T1p, W2r, b2, out, NTOT, OUTD, HIDD);
    k_agg<<<NDST, OUTD / 4>>>(Z2p, out + (size_t)NSRC * OUTD);
}

// round 7
// speedup vs baseline: 1.4713x; 1.4713x over previous
#include <cuda_runtime.h>
#include <cuda_bf16.h>
#include <cstdint>

// Problem constants (fixed shapes per reference)
#define NSRC  10000
#define NDST  10000
#define NTOT  20000
#define INS   512
#define IND   256
#define HIDD  512
#define OUTD  256
#define NEDGE 160000
#define EPSB  1e-5f

// ---------------------------------------------------------------------------
// PTX helpers — ONLY sm_80-baseline instructions (harness compiles via
// compute_103 virtual arch: tcgen05/TMEM are unavailable).
// ---------------------------------------------------------------------------
#define SWZ(o) ((o) ^ (((o) >> 3) & 0x70))

__device__ __forceinline__ uint32_t smem_to_u32(const void* p) {
    uint32_t a;
    asm("{ .reg .u64 t; cvta.to.shared.u64 t, %1; cvt.u32.u64 %0, t; }"
        : "=r"(a) : "l"(p));
    return a;
}

#define CP16(dst, src) \
    asm volatile("cp.async.cg.shared.global [%0], [%1], 16;" \
                 :: "r"(dst), "l"(src) : "memory")
#define CP_COMMIT() asm volatile("cp.async.commit_group;" ::: "memory")
#define CP_WAIT1()  asm volatile("cp.async.wait_group 1;" ::: "memory")
#define CP_WAIT0()  asm volatile("cp.async.wait_group 0;" ::: "memory")

#define LDSM4(r, addr) \
    asm volatile("ldmatrix.sync.aligned.m8n8.x4.shared.b16 {%0,%1,%2,%3}, [%4];" \
                 : "=r"((r)[0]), "=r"((r)[1]), "=r"((r)[2]), "=r"((r)[3]) \
                 : "r"(addr))

#define MMA16816(d, a, b) \
    asm volatile("mma.sync.aligned.m16n8k16.row.col.f32.bf16.bf16.f32 " \
                 "{%0,%1,%2,%3}, {%4,%5,%6,%7}, {%8,%9}, {%0,%1,%2,%3};" \
                 : "+f"((d)[0]), "+f"((d)[1]), "+f"((d)[2]), "+f"((d)[3]) \
                 : "r"((a)[0]), "r"((a)[1]), "r"((a)[2]), "r"((a)[3]), \
                   "r"((b)[0]), "r"((b)[1]))

// ---------------------------------------------------------------------------
// Scratch (static __device__ — no allocations allowed)
// ---------------------------------------------------------------------------
#define O_WSRC 0
#define O_WDST 262144
#define O_W1L  393216
#define O_W1R  655360
#define O_W2L  917504
#define O_W2R  1048576
#define WTOT   1179648

__device__ __align__(16) __nv_bfloat16 g_Wh[WTOT],  g_Wl[WTOT];
__device__ __align__(16) __nv_bfloat16 g_xsh[NSRC * INS], g_xsl[NSRC * INS];
__device__ __align__(16) __nv_bfloat16 g_xdh[NDST * IND], g_xdl[NDST * IND];
__device__ __align__(16) __nv_bfloat16 g_Xh[NTOT * HIDD], g_Xl[NTOT * HIDD];
__device__ __align__(16) __nv_bfloat16 g_Yh[NTOT * HIDD], g_Yl[NTOT * HIDD];
__device__ __align__(16) float g_Z1[NSRC * HIDD];
__device__ __align__(16) float g_T1[NTOT * HIDD];
__device__ __align__(16) float g_Z2[NSRC * OUTD];
__device__ int   g_edges[2 * NEDGE];
__device__ int   g_is64;
__device__ int   g_cnt[NDST];
__device__ int   g_off[NDST];
__device__ int   g_cur[NDST];
__device__ int   g_csr[NEDGE];
__device__ float g_colsum[HIDD];
__device__ float g_colsumsq[HIDD];
__device__ float g_sc[HIDD];
__device__ float g_sh[HIDD];

// ---------------------------------------------------------------------------
// Edge dtype detection + canonicalization (int32 vs int64 edge_index)
// ---------------------------------------------------------------------------
__global__ void k_detect(const void* p) {
    const int* q = (const int*)p;
    int all0 = 1;
    for (int i = 1; i < 64; i += 2)
        if (q[i] != 0) all0 = 0;
    g_is64 = all0;
}
__global__ void k_convert(const void* p) {
    int i = blockIdx.x * blockDim.x + threadIdx.x;
    if (i < 2 * NEDGE)
        g_edges[i] = g_is64 ? (int)((const long long*)p)[i] : ((const int*)p)[i];
}

// ---------------------------------------------------------------------------
// Graph preprocessing: histogram -> scan -> CSR fill
// ---------------------------------------------------------------------------
__global__ void k_zero() {
    int i = blockIdx.x * blockDim.x + threadIdx.x;
    if (i < NDST) g_cnt[i] = 0;
    if (i < HIDD) { g_colsum[i] = 0.f; g_colsumsq[i] = 0.f; }
}
__global__ void k_hist() {
    int i = blockIdx.x * blockDim.x + threadIdx.x;
    if (i < NEDGE) {
        unsigned d = (unsigned)(g_edges[NEDGE + i] - NSRC);
        if (d < NDST) atomicAdd(&g_cnt[d], 1);
    }
}
__global__ void k_scan() {
    __shared__ int part[1024];
    const int PER = 10;
    int t = threadIdx.x, base = t * PER, loc[PER], s = 0;
#pragma unroll
    for (int i = 0; i < PER; i++) {
        int idx = base + i;
        int v = (idx < NDST) ? g_cnt[idx] : 0;
        loc[i] = s; s += v;
    }
    part[t] = s;
    __syncthreads();
    for (int d = 1; d < 1024; d <<= 1) {
        int v = (t >= d) ? part[t - d] : 0;
        __syncthreads();
        part[t] += v;
        __syncthreads();
    }
    int ex = (t == 0) ? 0 : part[t - 1];
#pragma unroll
    for (int i = 0; i < PER; i++) {
        int idx = base + i;
        if (idx < NDST) { int o = ex + loc[i]; g_off[idx] = o; g_cur[idx] = o; }
    }
}
__global__ void k_fill() {
    int i = blockIdx.x * blockDim.x + threadIdx.x;
    if (i < NEDGE) {
        unsigned d = (unsigned)(g_edges[NEDGE + i] - NSRC);
        unsigned s = (unsigned)g_edges[i];
        if (d < NDST && s < NSRC) {
            int p = atomicAdd(&g_cur[d], 1);
            if (p < NEDGE) g_csr[p] = (int)s;
        }
    }
}

// ---------------------------------------------------------------------------
// fp32 -> bf16 (hi, lo) split
// ---------------------------------------------------------------------------
__global__ void k_split(const float4* __restrict__ x,
                        __nv_bfloat16* __restrict__ h,
                        __nv_bfloat16* __restrict__ l, int n4) {
    int i = blockIdx.x * blockDim.x + threadIdx.x;
    if (i >= n4) return;
    float4 v = x[i];
    float f[4] = {v.x, v.y, v.z, v.w};
    __nv_bfloat16 hb[4], lb[4];
#pragma unroll
    for (int j = 0; j < 4; j++) {
        hb[j] = __float2bfloat16(f[j]);
        lb[j] = __float2bfloat16(f[j] - __bfloat162float(hb[j]));
    }
    __nv_bfloat162* hp = (__nv_bfloat162*)h + i * 2;
    __nv_bfloat162* lp = (__nv_bfloat162*)l + i * 2;
    hp[0] = __halves2bfloat162(hb[0], hb[1]);
    hp[1] = __halves2bfloat162(hb[2], hb[3]);
    lp[0] = __halves2bfloat162(lb[0], lb[1]);
    lp[1] = __halves2bfloat162(lb[2], lb[3]);
}

// ---------------------------------------------------------------------------
// Warp-MMA bf16-split GEMM: C[M,N] = (Ah+Al)[M,K] @ (Bh+Bl)[N,K]^T (+ bias)
// 128x128 CTA tile, 8 warps (4M x 2N), warp tile 32x64, m16n8k16 HMMA,
// 3 MMAs per product term (hi*hi + hi*lo + lo*hi), cp.async double buffer.
// Epilogue writes fp32 (Cf) and/or bf16 split (Ch, Cl).
// ---------------------------------------------------------------------------
#define TG_SMEM (2 * 65536)

__global__ void __launch_bounds__(256) k_mgemm(
    const __nv_bfloat16* __restrict__ Ah, const __nv_bfloat16* __restrict__ Al,
    const __nv_bfloat16* __restrict__ Bh, const __nv_bfloat16* __restrict__ Bl,
    const float* __restrict__ bias,
    float* __restrict__ Cf,
    __nv_bfloat16* __restrict__ Ch, __nv_bfloat16* __restrict__ Cl,
    int M, int N, int K)
{
    extern __shared__ __align__(1024) char smem[];
    const uint32_t smb = smem_to_u32(smem);
    const int tid = threadIdx.x, wid = tid >> 5, lane = tid & 31;
    const int m0 = blockIdx.y * 128, n0 = blockIdx.x * 128;
    const int warp_m = (wid >> 1) * 32;     // 4 warps along M
    const int warp_n = (wid & 1) * 64;      // 2 warps along N

    float acc[2][8][4] = {};

    const int NC = K >> 6;   // K chunks of 64

    // buffer layout per 64KB stage: Ah @0, Al @16K, Bh @32K, Bl @48K
    auto load_chunk = [&](int c, int buf) {
        uint32_t bo = smb + (uint32_t)buf * 65536;
        int k0 = c << 6;
#pragma unroll
        for (int s = 0; s < 4; s++) {
            int seg = tid + s * 256;          // 0..1023
            int row = seg >> 3;               // 0..127
            int sg  = seg & 7;                // 16B segment within 128B row
            uint32_t sw = SWZ((uint32_t)(row * 128 + sg * 16));
            size_t acol = (size_t)(k0 + sg * 8);
            int gm = m0 + row; if (gm >= M) gm = M - 1;   // clamp: never stored
            int gn = n0 + row;
            CP16(bo + sw,         (const char*)(Ah + (size_t)gm * K + acol));
            CP16(bo + 16384 + sw, (const char*)(Al + (size_t)gm * K + acol));
            CP16(bo + 32768 + sw, (const char*)(Bh + (size_t)gn * K + acol));
            CP16(bo + 49152 + sw, (const char*)(Bl + (size_t)gn * K + acol));
        }
        CP_COMMIT();
    };

    load_chunk(0, 0);
    if (NC > 1) load_chunk(1, 1);

    const int q  = lane >> 3;   // ldmatrix sub-matrix index
    const int rr = lane & 7;

    for (int c = 0; c < NC; c++) {
        if (c + 1 < NC) CP_WAIT1(); else CP_WAIT0();
        __syncthreads();
        uint32_t bo = smb + (uint32_t)(c & 1) * 65536;
#pragma unroll
        for (int ks = 0; ks < 4; ks++) {
            const uint32_t kb = (uint32_t)(ks * 32 + (q >> 1) * 16);
            uint32_t ah[2][4], al[2][4];
#pragma unroll
            for (int mi = 0; mi < 2; mi++) {
                uint32_t arow = (uint32_t)(warp_m + mi * 16 + (q & 1) * 8 + rr);
                uint32_t ad = bo + SWZ(arow * 128 + kb);
                LDSM4(ah[mi], ad);
                LDSM4(al[mi], ad + 16384);
            }
            uint32_t bhf[4][4], blf[4][4];
#pragma unroll
            for (int nj = 0; nj < 4; nj++) {
                uint32_t brow = (uint32_t)(warp_n + nj * 16 + (q & 1) * 8 + rr);
                uint32_t bd = bo + 32768 + SWZ(brow * 128 + kb);
                LDSM4(bhf[nj], bd);
                LDSM4(blf[nj], bd + 16384);
            }
#pragma unroll
            for (int mi = 0; mi < 2; mi++)
#pragma unroll
                for (int nj = 0; nj < 4; nj++)
#pragma unroll
                    for (int sub = 0; sub < 2; sub++) {
                        const int ni = nj * 2 + sub;
                        uint32_t bh2[2] = { bhf[nj][sub], bhf[nj][sub + 2] };
                        uint32_t bl2[2] = { blf[nj][sub], blf[nj][sub + 2] };
                        MMA16816(acc[mi][ni], ah[mi], bh2);   // hi*hi
                        MMA16816(acc[mi][ni], ah[mi], bl2);   // hi*lo
                        MMA16816(acc[mi][ni], al[mi], bh2);   // lo*hi
                    }
        }
        __syncthreads();
        if (c + 2 < NC) load_chunk(c + 2, c & 1);
    }

    // --- epilogue ---
#pragma unroll
    for (int mi = 0; mi < 2; mi++) {
        int mrow = m0 + warp_m + mi * 16 + (lane >> 2);
#pragma unroll
        for (int half = 0; half < 2; half++) {
            int gm = mrow + half * 8;
            if (gm < M) {
#pragma unroll
                for (int ni = 0; ni < 8; ni++) {
                    int gn = n0 + warp_n + ni * 8 + (lane & 3) * 2;
                    float v0 = acc[mi][ni][half * 2 + 0];
                    float v1 = acc[mi][ni][half * 2 + 1];
                    if (bias) { v0 += bias[gn]; v1 += bias[gn + 1]; }
                    size_t o = (size_t)gm * N + gn;
                    if (Cf) *(float2*)(Cf + o) = make_float2(v0, v1);
                    if (Ch) {
                        __nv_bfloat16 h0 = __float2bfloat16(v0);
                        __nv_bfloat16 h1 = __float2bfloat16(v1);
                        *(__nv_bfloat162*)(Ch + o) = __halves2bfloat162(h0, h1);
                        *(__nv_bfloat162*)(Cl + o) = __halves2bfloat162(
                            __float2bfloat16(v0 - __bfloat162float(h0)),
                            __float2bfloat16(v1 - __bfloat162float(h1)));
                    }
                }
            }
        }
    }
}

// ---------------------------------------------------------------------------
// CSR aggregation: C[d] += mean_{s in nbrs(d)} Z[s]
// ---------------------------------------------------------------------------
__global__ void k_agg(const float* __restrict__ Z, float* __restrict__ C) {
    int d = blockIdx.x;
    int deg = g_cnt[d];
    if (deg == 0) return;
    int W4 = blockDim.x;
    const float4* Z4 = (const float4*)Z;
    float4 acc = make_float4(0.f, 0.f, 0.f, 0.f);
    int o = g_off[d];
    for (int e = 0; e < deg; e++) {
        int s = g_csr[o + e];
        float4 v = Z4[(size_t)s * W4 + threadIdx.x];
        acc.x += v.x; acc.y += v.y; acc.z += v.z; acc.w += v.w;
    }
    float inv = 1.0f / (float)deg;
    float4* C4 = (float4*)C;
    size_t oi = (size_t)d * W4 + threadIdx.x;
    float4 c = C4[oi];
    c.x += acc.x * inv; c.y += acc.y * inv;
    c.z += acc.z * inv; c.w += acc.w * inv;
    C4[oi] = c;
}

// ---------------------------------------------------------------------------
// BatchNorm (training stats) + ReLU; apply writes bf16 hi/lo for layer 2
// ---------------------------------------------------------------------------
__global__ void k_bnstats(const float* __restrict__ T) {
    const float4* T4 = (const float4*)T;
    float4 s = make_float4(0.f, 0.f, 0.f, 0.f);
    float4 q = make_float4(0.f, 0.f, 0.f, 0.f);
    for (int r = blockIdx.x; r < NTOT; r += gridDim.x) {
        float4 v = T4[(size_t)r * (HIDD / 4) + threadIdx.x];
        s.x += v.x; s.y += v.y; s.z += v.z; s.w += v.w;
        q.x += v.x * v.x; q.y += v.y * v.y; q.z += v.z * v.z; q.w += v.w * v.w;
    }
    int c = threadIdx.x * 4;
    atomicAdd(&g_colsum[c + 0], s.x); atomicAdd(&g_colsum[c + 1], s.y);
    atomicAdd(&g_colsum[c + 2], s.z); atomicAdd(&g_colsum[c + 3], s.w);
    atomicAdd(&g_colsumsq[c + 0], q.x); atomicAdd(&g_colsumsq[c + 1], q.y);
    atomicAdd(&g_colsumsq[c + 2], q.z); atomicAdd(&g_colsumsq[c + 3], q.w);
}
__global__ void k_bncoef(const float* __restrict__ gamma,
                         const float* __restrict__ beta) {
    int c = threadIdx.x;
    if (c < HIDD) {
        float mu  = g_colsum[c]   * (1.0f / NTOT);
        float var = g_colsumsq[c] * (1.0f / NTOT) - mu * mu;
        float s = gamma[c] * rsqrtf(var + EPSB);
        g_sc[c] = s;
        g_sh[c] = beta[c] - mu * s;
    }
}
__global__ void k_bnapply(const float* __restrict__ T,
                          __nv_bfloat16* __restrict__ Yh,
                          __nv_bfloat16* __restrict__ Yl) {
    int idx = blockIdx.x * blockDim.x + threadIdx.x;   // float4 index
    const int TOT4 = NTOT * (HIDD / 4);
    if (idx >= TOT4) return;
    int c4 = idx & (HIDD / 4 - 1);
    float4 v = ((const float4*)T)[idx];
    float4 s = ((const float4*)g_sc)[c4];
    float4 h = ((const float4*)g_sh)[c4];
    float f[4];
    f[0] = fmaxf(fmaf(v.x, s.x, h.x), 0.f);
    f[1] = fmaxf(fmaf(v.y, s.y, h.y), 0.f);
    f[2] = fmaxf(fmaf(v.z, s.z, h.z), 0.f);
    f[3] = fmaxf(fmaf(v.w, s.w, h.w), 0.f);
    __nv_bfloat16 hb[4], lb[4];
#pragma unroll
    for (int j = 0; j < 4; j++) {
        hb[j] = __float2bfloat16(f[j]);
        lb[j] = __float2bfloat16(f[j] - __bfloat162float(hb[j]));
    }
    __nv_bfloat162* hp = (__nv_bfloat162*)Yh + idx * 2;
    __nv_bfloat162* lp = (__nv_bfloat162*)Yl + idx * 2;
    hp[0] = __halves2bfloat162(hb[0], hb[1]);
    hp[1] = __halves2bfloat162(hb[2], hb[3]);
    lp[0] = __halves2bfloat162(lb[0], lb[1]);
    lp[1] = __halves2bfloat162(lb[2], lb[3]);
}

// ---------------------------------------------------------------------------
// Launch
// ---------------------------------------------------------------------------
extern "C" void kernel_launch(void* const* d_in, const int* in_sizes, int n_in,
                              void* d_out, int out_size) {
    const float* x_src = (const float*)d_in[0];
    const float* x_dst = (const float*)d_in[1];
    const float* W_src = (const float*)d_in[2];
    const float* b_src = (const float*)d_in[3];
    const float* W_dst = (const float*)d_in[4];
    const float* b_dst = (const float*)d_in[5];
    const float* W1l   = (const float*)d_in[6];
    const float* b1    = (const float*)d_in[7];
    const float* W1r   = (const float*)d_in[8];
    const float* W2l   = (const float*)d_in[9];
    const float* b2    = (const float*)d_in[10];
    const float* W2r   = (const float*)d_in[11];
    const float* gamma = (const float*)d_in[12];
    const float* beta  = (const float*)d_in[13];
    const void*  ei    = d_in[14];
    float* out = (float*)d_out;

    static int attr_set = 0;
    if (!attr_set) {
        cudaFuncSetAttribute(k_mgemm, cudaFuncAttributeMaxDynamicSharedMemorySize, TG_SMEM);
        attr_set = 1;
    }

    __nv_bfloat16 *Whp, *Wlp, *xshp, *xslp, *xdhp, *xdlp, *Xhp, *Xlp, *Yhp, *Ylp;
    float *Z1p, *T1p, *Z2p;
    cudaGetSymbolAddress((void**)&Whp,  g_Wh);
    cudaGetSymbolAddress((void**)&Wlp,  g_Wl);
    cudaGetSymbolAddress((void**)&xshp, g_xsh);
    cudaGetSymbolAddress((void**)&xslp, g_xsl);
    cudaGetSymbolAddress((void**)&xdhp, g_xdh);
    cudaGetSymbolAddress((void**)&xdlp, g_xdl);
    cudaGetSymbolAddress((void**)&Xhp,  g_Xh);
    cudaGetSymbolAddress((void**)&Xlp,  g_Xl);
    cudaGetSymbolAddress((void**)&Yhp,  g_Yh);
    cudaGetSymbolAddress((void**)&Ylp,  g_Yl);
    cudaGetSymbolAddress((void**)&Z1p,  g_Z1);
    cudaGetSymbolAddress((void**)&T1p,  g_T1);
    cudaGetSymbolAddress((void**)&Z2p,  g_Z2);

    // edge canonicalization + CSR build
    k_detect<<<1, 1>>>(ei);
    k_convert<<<(2 * NEDGE + 255) / 256, 256>>>(ei);
    k_zero<<<(NDST + 255) / 256, 256>>>();
    k_hist<<<(NEDGE + 255) / 256, 256>>>();
    k_scan<<<1, 1024>>>();
    k_fill<<<(NEDGE + 255) / 256, 256>>>();

    // bf16 splits of raw inputs + weights
    auto SPL = [](const float* x, __nv_bfloat16* h, __nv_bfloat16* l, int n) {
        int n4 = n / 4;
        k_split<<<(n4 + 255) / 256, 256>>>((const float4*)x, h, l, n4);
    };
    SPL(x_src, xshp, xslp, NSRC * INS);
    SPL(x_dst, xdhp, xdlp, NDST * IND);
    SPL(W_src, Whp + O_WSRC, Wlp + O_WSRC, HIDD * INS);
    SPL(W_dst, Whp + O_WDST, Wlp + O_WDST, HIDD * IND);
    SPL(W1l,   Whp + O_W1L,  Wlp + O_W1L,  HIDD * HIDD);
    SPL(W1r,   Whp + O_W1R,  Wlp + O_W1R,  HIDD * HIDD);
    SPL(W2l,   Whp + O_W2L,  Wlp + O_W2L,  OUTD * HIDD);
    SPL(W2r,   Whp + O_W2R,  Wlp + O_W2R,  OUTD * HIDD);

    // input projections -> X = concat(h_src, h_dst)  (write bf16 split only)
    k_mgemm<<<dim3(HIDD / 128, (NSRC + 127) / 128), 256, TG_SMEM>>>(
        xshp, xslp, Whp + O_WSRC, Wlp + O_WSRC, b_src,
        nullptr, Xhp, Xlp, NSRC, HIDD, INS);
    k_mgemm<<<dim3(HIDD / 128, (NDST + 127) / 128), 256, TG_SMEM>>>(
        xdhp, xdlp, Whp + O_WDST, Wlp + O_WDST, b_dst,
        nullptr, Xhp + (size_t)NSRC * HIDD, Xlp + (size_t)NSRC * HIDD, NDST, HIDD, IND);

    // layer 1: Z1 = X[:10k] @ W1l.T ; T1 = X @ W1r.T + b1 ; T1[dst] += mean(Z1[src])
    k_mgemm<<<dim3(HIDD / 128, (NSRC + 127) / 128), 256, TG_SMEM>>>(
        Xhp, Xlp, Whp + O_W1L, Wlp + O_W1L, nullptr,
        Z1p, nullptr, nullptr, NSRC, HIDD, HIDD);
    k_mgemm<<<dim3(HIDD / 128, (NTOT + 127) / 128), 256, TG_SMEM>>>(
        Xhp, Xlp, Whp + O_W1R, Wlp + O_W1R, b1,
        T1p, nullptr, nullptr, NTOT, HIDD, HIDD);
    k_agg<<<NDST, HIDD / 4>>>(Z1p, T1p + (size_t)NSRC * HIDD);

    // BatchNorm + ReLU -> bf16 split Y
    k_bnstats<<<256, HIDD / 4>>>(T1p);
    k_bncoef<<<1, HIDD>>>(gamma, beta);
    k_bnapply<<<(NTOT * (HIDD / 4) + 255) / 256, 256>>>(T1p, Yhp, Ylp);

    // layer 2: Z2 = Y[:10k] @ W2l.T ; OUT = Y @ W2r.T + b2 ; OUT[dst] += mean(Z2[src])
    k_mgemm<<<dim3(OUTD / 128, (NSRC + 127) / 128), 256, TG_SMEM>>>(
        Yhp, Ylp, Whp + O_W2L, Wlp + O_W2L, nullptr,
        Z2p, nullptr, nullptr, NSRC, OUTD, HIDD);
    k_mgemm<<<dim3(OUTD / 128, (NTOT + 127) / 128), 256, TG_SMEM>>>(
        Yhp, Ylp, Whp + O_W2R, Wlp + O_W2R, b2,
        out, nullptr, nullptr, NTOT, OUTD, HIDD);
    k_agg<<<NDST, OUTD / 4>>>(Z2p, out + (size_t)NSRC * OUTD);
}

// round 8
// speedup vs baseline: 1.9944x; 1.3555x over previous
#include <cuda_runtime.h>
#include <cuda_bf16.h>
#include <cstdint>

// Problem constants (fixed shapes per reference)
#define NSRC  10000
#define NDST  10000
#define NTOT  20000
#define INS   512
#define IND   256
#define HIDD  512
#define OUTD  256
#define NEDGE 160000
#define EPSB  1e-5f

// ---------------------------------------------------------------------------
// PTX helpers — sm_80-baseline only (harness compiles via compute_103
// virtual arch: tcgen05/TMEM unavailable).
// ---------------------------------------------------------------------------
#define SWZ64(o) ((o) ^ (((o) >> 3) & 0x30))   // 64B-row swizzle (8x64B atom)

__device__ __forceinline__ uint32_t smem_to_u32(const void* p) {
    uint32_t a;
    asm("{ .reg .u64 t; cvta.to.shared.u64 t, %1; cvt.u32.u64 %0, t; }"
        : "=r"(a) : "l"(p));
    return a;
}

#define CP16(dst, src) \
    asm volatile("cp.async.cg.shared.global [%0], [%1], 16;" \
                 :: "r"(dst), "l"(src) : "memory")
#define CP_COMMIT() asm volatile("cp.async.commit_group;" ::: "memory")
#define CP_WAIT2()  asm volatile("cp.async.wait_group 2;" ::: "memory")
#define CP_WAIT1()  asm volatile("cp.async.wait_group 1;" ::: "memory")
#define CP_WAIT0()  asm volatile("cp.async.wait_group 0;" ::: "memory")

#define LDSM4(r, addr) \
    asm volatile("ldmatrix.sync.aligned.m8n8.x4.shared.b16 {%0,%1,%2,%3}, [%4];" \
                 : "=r"((r)[0]), "=r"((r)[1]), "=r"((r)[2]), "=r"((r)[3]) \
                 : "r"(addr))

#define MMA16816(d, a, b) \
    asm volatile("mma.sync.aligned.m16n8k16.row.col.f32.bf16.bf16.f32 " \
                 "{%0,%1,%2,%3}, {%4,%5,%6,%7}, {%8,%9}, {%0,%1,%2,%3};" \
                 : "+f"((d)[0]), "+f"((d)[1]), "+f"((d)[2]), "+f"((d)[3]) \
                 : "r"((a)[0]), "r"((a)[1]), "r"((a)[2]), "r"((a)[3]), \
                   "r"((b)[0]), "r"((b)[1]))

// ---------------------------------------------------------------------------
// Scratch (static __device__ — no allocations allowed)
// ---------------------------------------------------------------------------
#define O_WSRC 0
#define O_WDST 262144
#define O_W1L  393216
#define O_W1R  655360
#define O_W2L  917504
#define O_W2R  1048576
#define WTOT   1179648

__device__ __align__(16) __nv_bfloat16 g_Wh[WTOT],  g_Wl[WTOT];
__device__ __align__(16) __nv_bfloat16 g_xsh[NSRC * INS], g_xsl[NSRC * INS];
__device__ __align__(16) __nv_bfloat16 g_xdh[NDST * IND], g_xdl[NDST * IND];
__device__ __align__(16) __nv_bfloat16 g_Xh[NTOT * HIDD], g_Xl[NTOT * HIDD];
__device__ __align__(16) __nv_bfloat16 g_Yh[NTOT * HIDD], g_Yl[NTOT * HIDD];
__device__ __align__(16) float g_Z1[NSRC * HIDD];
__device__ __align__(16) float g_T1[NTOT * HIDD];
__device__ __align__(16) float g_Z2[NSRC * OUTD];
__device__ int   g_edges[2 * NEDGE];
__device__ int   g_is64;
__device__ int   g_cnt[NDST];
__device__ int   g_off[NDST];
__device__ int   g_cur[NDST];
__device__ int   g_csr[NEDGE];
__device__ float g_colsum[HIDD];
__device__ float g_colsumsq[HIDD];
__device__ float g_sc[HIDD];
__device__ float g_sh[HIDD];

// ---------------------------------------------------------------------------
// Edge dtype detection + canonicalization (int32 vs int64 edge_index)
// ---------------------------------------------------------------------------
__global__ void k_detect(const void* p) {
    const int* q = (const int*)p;
    int all0 = 1;
    for (int i = 1; i < 64; i += 2)
        if (q[i] != 0) all0 = 0;
    g_is64 = all0;
}
__global__ void k_convert(const void* p) {
    int i = blockIdx.x * blockDim.x + threadIdx.x;
    if (i < 2 * NEDGE)
        g_edges[i] = g_is64 ? (int)((const long long*)p)[i] : ((const int*)p)[i];
}

// ---------------------------------------------------------------------------
// Graph preprocessing: histogram -> scan -> CSR fill
// ---------------------------------------------------------------------------
__global__ void k_zero() {
    int i = blockIdx.x * blockDim.x + threadIdx.x;
    if (i < NDST) g_cnt[i] = 0;
    if (i < HIDD) { g_colsum[i] = 0.f; g_colsumsq[i] = 0.f; }
}
__global__ void k_hist() {
    int i = blockIdx.x * blockDim.x + threadIdx.x;
    if (i < NEDGE) {
        unsigned d = (unsigned)(g_edges[NEDGE + i] - NSRC);
        if (d < NDST) atomicAdd(&g_cnt[d], 1);
    }
}
__global__ void k_scan() {
    __shared__ int part[1024];
    const int PER = 10;
    int t = threadIdx.x, base = t * PER, loc[PER], s = 0;
#pragma unroll
    for (int i = 0; i < PER; i++) {
        int idx = base + i;
        int v = (idx < NDST) ? g_cnt[idx] : 0;
        loc[i] = s; s += v;
    }
    part[t] = s;
    __syncthreads();
    for (int d = 1; d < 1024; d <<= 1) {
        int v = (t >= d) ? part[t - d] : 0;
        __syncthreads();
        part[t] += v;
        __syncthreads();
    }
    int ex = (t == 0) ? 0 : part[t - 1];
#pragma unroll
    for (int i = 0; i < PER; i++) {
        int idx = base + i;
        if (idx < NDST) { int o = ex + loc[i]; g_off[idx] = o; g_cur[idx] = o; }
    }
}
__global__ void k_fill() {
    int i = blockIdx.x * blockDim.x + threadIdx.x;
    if (i < NEDGE) {
        unsigned d = (unsigned)(g_edges[NEDGE + i] - NSRC);
        unsigned s = (unsigned)g_edges[i];
        if (d < NDST && s < NSRC) {
            int p = atomicAdd(&g_cur[d], 1);
            if (p < NEDGE) g_csr[p] = (int)s;
        }
    }
}

// ---------------------------------------------------------------------------
// fp32 -> bf16 (hi, lo) split
// ---------------------------------------------------------------------------
__global__ void k_split(const float4* __restrict__ x,
                        __nv_bfloat16* __restrict__ h,
                        __nv_bfloat16* __restrict__ l, int n4) {
    int i = blockIdx.x * blockDim.x + threadIdx.x;
    if (i >= n4) return;
    float4 v = x[i];
    float f[4] = {v.x, v.y, v.z, v.w};
    __nv_bfloat16 hb[4], lb[4];
#pragma unroll
    for (int j = 0; j < 4; j++) {
        hb[j] = __float2bfloat16(f[j]);
        lb[j] = __float2bfloat16(f[j] - __bfloat162float(hb[j]));
    }
    __nv_bfloat162* hp = (__nv_bfloat162*)h + i * 2;
    __nv_bfloat162* lp = (__nv_bfloat162*)l + i * 2;
    hp[0] = __halves2bfloat162(hb[0], hb[1]);
    hp[1] = __halves2bfloat162(hb[2], hb[3]);
    lp[0] = __halves2bfloat162(lb[0], lb[1]);
    lp[1] = __halves2bfloat162(lb[2], lb[3]);
}

// ---------------------------------------------------------------------------
// Warp-MMA bf16-split GEMM: C[M,N] = (Ah+Al)[M,K] @ (Bh+Bl)[N,K]^T (+ bias)
// 128x128 CTA tile, 8 warps (4M x 2N), warp tile 32x64, m16n8k16 HMMA,
// 3 MMAs per term (hi*hi + hi*lo + lo*hi).
// 4-stage cp.async pipeline, chunk K=32 (32KB/stage), ONE barrier per chunk:
//   wait(chunk c) -> barrier -> issue loads for c+3 -> compute c
// Epilogue writes fp32 (Cf) and/or bf16 split (Ch, Cl).
// ---------------------------------------------------------------------------
#define STG_BYTES 32768
#define TG_SMEM   (4 * STG_BYTES)

__global__ void __launch_bounds__(256) k_mgemm(
    const __nv_bfloat16* __restrict__ Ah, const __nv_bfloat16* __restrict__ Al,
    const __nv_bfloat16* __restrict__ Bh, const __nv_bfloat16* __restrict__ Bl,
    const float* __restrict__ bias,
    float* __restrict__ Cf,
    __nv_bfloat16* __restrict__ Ch, __nv_bfloat16* __restrict__ Cl,
    int M, int N, int K)
{
    extern __shared__ __align__(1024) char smem[];
    const uint32_t smb = smem_to_u32(smem);
    const int tid = threadIdx.x, wid = tid >> 5, lane = tid & 31;
    const int m0 = blockIdx.y * 128, n0 = blockIdx.x * 128;
    const int warp_m = (wid >> 1) * 32;     // 4 warps along M
    const int warp_n = (wid & 1) * 64;      // 2 warps along N

    float acc[2][8][4] = {};

    const int NC = K >> 5;   // K chunks of 32

    // stage layout: Ah @0, Al @8K, Bh @16K, Bl @24K  (64B rows, SW64 swizzle)
    auto load_chunk = [&](int c, int buf) {
        uint32_t bo = smb + (uint32_t)buf * STG_BYTES;
        int k0 = c << 5;
#pragma unroll
        for (int it = 0; it < 2; it++) {
            int seg = tid + it * 256;        // 0..511
            int row = seg >> 2;              // 0..127
            int sg  = seg & 3;               // 16B segment in 64B row
            uint32_t sw = SWZ64((uint32_t)(row * 64 + sg * 16));
            size_t acol = (size_t)(k0 + sg * 8);
            int gm = m0 + row; if (gm >= M) gm = M - 1;   // clamp: never stored
            int gn = n0 + row;
            CP16(bo + sw,         (const char*)(Ah + (size_t)gm * K + acol));
            CP16(bo + 8192  + sw, (const char*)(Al + (size_t)gm * K + acol));
            CP16(bo + 16384 + sw, (const char*)(Bh + (size_t)gn * K + acol));
            CP16(bo + 24576 + sw, (const char*)(Bl + (size_t)gn * K + acol));
        }
        CP_COMMIT();
    };

    load_chunk(0, 0);
    load_chunk(1, 1);
    load_chunk(2, 2);

    const int q  = lane >> 3;   // ldmatrix sub-matrix index
    const int rr = lane & 7;

    for (int c = 0; c < NC; c++) {
        int rem = NC - 1 - c;
        if (rem >= 2) CP_WAIT2(); else if (rem == 1) CP_WAIT1(); else CP_WAIT0();
        __syncthreads();                        // chunk-c data visible to all;
                                                // all done reading buf (c-1)%4
        if (c + 3 < NC) load_chunk(c + 3, (c + 3) & 3);

        uint32_t bo = smb + (uint32_t)(c & 3) * STG_BYTES;
#pragma unroll
        for (int ks = 0; ks < 2; ks++) {
            const uint32_t kb = (uint32_t)(ks * 32 + (q >> 1) * 16);
            uint32_t ahf[2][4], alf[2][4];
#pragma unroll
            for (int mi = 0; mi < 2; mi++) {
                uint32_t arow = (uint32_t)(warp_m + mi * 16 + (q & 1) * 8 + rr);
                uint32_t ad = bo + SWZ64(arow * 64 + kb);
                LDSM4(ahf[mi], ad);
                LDSM4(alf[mi], ad + 8192);
            }
            uint32_t bhf[4][4], blf[4][4];
#pragma unroll
            for (int nj = 0; nj < 4; nj++) {
                uint32_t brow = (uint32_t)(warp_n + nj * 16 + (q & 1) * 8 + rr);
                uint32_t bd = bo + 16384 + SWZ64(brow * 64 + kb);
                LDSM4(bhf[nj], bd);
                LDSM4(blf[nj], bd + 8192);
            }
#pragma unroll
            for (int mi = 0; mi < 2; mi++)
#pragma unroll
                for (int nj = 0; nj < 4; nj++)
#pragma unroll
                    for (int sub = 0; sub < 2; sub++) {
                        const int ni = nj * 2 + sub;
                        uint32_t bh2[2] = { bhf[nj][sub], bhf[nj][sub + 2] };
                        uint32_t bl2[2] = { blf[nj][sub], blf[nj][sub + 2] };
                        MMA16816(acc[mi][ni], ahf[mi], bh2);   // hi*hi
                        MMA16816(acc[mi][ni], ahf[mi], bl2);   // hi*lo
                        MMA16816(acc[mi][ni], alf[mi], bh2);   // lo*hi
                    }
        }
    }

    // --- epilogue ---
#pragma unroll
    for (int mi = 0; mi < 2; mi++) {
        int mrow = m0 + warp_m + mi * 16 + (lane >> 2);
#pragma unroll
        for (int half = 0; half < 2; half++) {
            int gm = mrow + half * 8;
            if (gm < M) {
#pragma unroll
                for (int ni = 0; ni < 8; ni++) {
                    int gn = n0 + warp_n + ni * 8 + (lane & 3) * 2;
                    float v0 = acc[mi][ni][half * 2 + 0];
                    float v1 = acc[mi][ni][half * 2 + 1];
                    if (bias) { v0 += bias[gn]; v1 += bias[gn + 1]; }
                    size_t o = (size_t)gm * N + gn;
                    if (Cf) *(float2*)(Cf + o) = make_float2(v0, v1);
                    if (Ch) {
                        __nv_bfloat16 h0 = __float2bfloat16(v0);
                        __nv_bfloat16 h1 = __float2bfloat16(v1);
                        *(__nv_bfloat162*)(Ch + o) = __halves2bfloat162(h0, h1);
                        *(__nv_bfloat162*)(Cl + o) = __halves2bfloat162(
                            __float2bfloat16(v0 - __bfloat162float(h0)),
                            __float2bfloat16(v1 - __bfloat162float(h1)));
                    }
                }
            }
        }
    }
}

// ---------------------------------------------------------------------------
// CSR aggregation: C[d] += mean_{s in nbrs(d)} Z[s]   (2-deep prefetch)
// ---------------------------------------------------------------------------
__global__ void k_agg(const float* __restrict__ Z, float* __restrict__ C) {
    int d = blockIdx.x;
    int deg = g_cnt[d];
    if (deg == 0) return;
    int W4 = blockDim.x;
    const float4* Z4 = (const float4*)Z;
    float4 acc = make_float4(0.f, 0.f, 0.f, 0.f);
    int o = g_off[d];
    int e = 0;
    for (; e + 2 <= deg; e += 2) {
        int s0 = g_csr[o + e], s1 = g_csr[o + e + 1];
        float4 v0 = Z4[(size_t)s0 * W4 + threadIdx.x];
        float4 v1 = Z4[(size_t)s1 * W4 + threadIdx.x];
        acc.x += v0.x + v1.x; acc.y += v0.y + v1.y;
        acc.z += v0.z + v1.z; acc.w += v0.w + v1.w;
    }
    if (e < deg) {
        int s = g_csr[o + e];
        float4 v = Z4[(size_t)s * W4 + threadIdx.x];
        acc.x += v.x; acc.y += v.y; acc.z += v.z; acc.w += v.w;
    }
    float inv = 1.0f / (float)deg;
    float4* C4 = (float4*)C;
    size_t oi = (size_t)d * W4 + threadIdx.x;
    float4 c = C4[oi];
    c.x += acc.x * inv; c.y += acc.y * inv;
    c.z += acc.z * inv; c.w += acc.w * inv;
    C4[oi] = c;
}

// ---------------------------------------------------------------------------
// BatchNorm (training stats) + ReLU; apply writes bf16 hi/lo for layer 2
// ---------------------------------------------------------------------------
__global__ void k_bnstats(const float* __restrict__ T) {
    const float4* T4 = (const float4*)T;
    float4 s = make_float4(0.f, 0.f, 0.f, 0.f);
    float4 q = make_float4(0.f, 0.f, 0.f, 0.f);
    for (int r = blockIdx.x; r < NTOT; r += gridDim.x) {
        float4 v = T4[(size_t)r * (HIDD / 4) + threadIdx.x];
        s.x += v.x; s.y += v.y; s.z += v.z; s.w += v.w;
        q.x += v.x * v.x; q.y += v.y * v.y; q.z += v.z * v.z; q.w += v.w * v.w;
    }
    int c = threadIdx.x * 4;
    atomicAdd(&g_colsum[c + 0], s.x); atomicAdd(&g_colsum[c + 1], s.y);
    atomicAdd(&g_colsum[c + 2], s.z); atomicAdd(&g_colsum[c + 3], s.w);
    atomicAdd(&g_colsumsq[c + 0], q.x); atomicAdd(&g_colsumsq[c + 1], q.y);
    atomicAdd(&g_colsumsq[c + 2], q.z); atomicAdd(&g_colsumsq[c + 3], q.w);
}
__global__ void k_bncoef(const float* __restrict__ gamma,
                         const float* __restrict__ beta) {
    int c = threadIdx.x;
    if (c < HIDD) {
        float mu  = g_colsum[c]   * (1.0f / NTOT);
        float var = g_colsumsq[c] * (1.0f / NTOT) - mu * mu;
        float s = gamma[c] * rsqrtf(var + EPSB);
        g_sc[c] = s;
        g_sh[c] = beta[c] - mu * s;
    }
}
__global__ void k_bnapply(const float* __restrict__ T,
                          __nv_bfloat16* __restrict__ Yh,
                          __nv_bfloat16* __restrict__ Yl) {
    int idx = blockIdx.x * blockDim.x + threadIdx.x;   // float4 index
    const int TOT4 = NTOT * (HIDD / 4);
    if (idx >= TOT4) return;
    int c4 = idx & (HIDD / 4 - 1);
    float4 v = ((const float4*)T)[idx];
    float4 s = ((const float4*)g_sc)[c4];
    float4 h = ((const float4*)g_sh)[c4];
    float f[4];
    f[0] = fmaxf(fmaf(v.x, s.x, h.x), 0.f);
    f[1] = fmaxf(fmaf(v.y, s.y, h.y), 0.f);
    f[2] = fmaxf(fmaf(v.z, s.z, h.z), 0.f);
    f[3] = fmaxf(fmaf(v.w, s.w, h.w), 0.f);
    __nv_bfloat16 hb[4], lb[4];
#pragma unroll
    for (int j = 0; j < 4; j++) {
        hb[j] = __float2bfloat16(f[j]);
        lb[j] = __float2bfloat16(f[j] - __bfloat162float(hb[j]));
    }
    __nv_bfloat162* hp = (__nv_bfloat162*)Yh + idx * 2;
    __nv_bfloat162* lp = (__nv_bfloat162*)Yl + idx * 2;
    hp[0] = __halves2bfloat162(hb[0], hb[1]);
    hp[1] = __halves2bfloat162(hb[2], hb[3]);
    lp[0] = __halves2bfloat162(lb[0], lb[1]);
    lp[1] = __halves2bfloat162(lb[2], lb[3]);
}

// ---------------------------------------------------------------------------
// Launch
// ---------------------------------------------------------------------------
extern "C" void kernel_launch(void* const* d_in, const int* in_sizes, int n_in,
                              void* d_out, int out_size) {
    const float* x_src = (const float*)d_in[0];
    const float* x_dst = (const float*)d_in[1];
    const float* W_src = (const float*)d_in[2];
    const float* b_src = (const float*)d_in[3];
    const float* W_dst = (const float*)d_in[4];
    const float* b_dst = (const float*)d_in[5];
    const float* W1l   = (const float*)d_in[6];
    const float* b1    = (const float*)d_in[7];
    const float* W1r   = (const float*)d_in[8];
    const float* W2l   = (const float*)d_in[9];
    const float* b2    = (const float*)d_in[10];
    const float* W2r   = (const float*)d_in[11];
    const float* gamma = (const float*)d_in[12];
    const float* beta  = (const float*)d_in[13];
    const void*  ei    = d_in[14];
    float* out = (float*)d_out;

    static int attr_set = 0;
    if (!attr_set) {
        cudaFuncSetAttribute(k_mgemm, cudaFuncAttributeMaxDynamicSharedMemorySize, TG_SMEM);
        attr_set = 1;
    }

    __nv_bfloat16 *Whp, *Wlp, *xshp, *xslp, *xdhp, *xdlp, *Xhp, *Xlp, *Yhp, *Ylp;
    float *Z1p, *T1p, *Z2p;
    cudaGetSymbolAddress((void**)&Whp,  g_Wh);
    cudaGetSymbolAddress((void**)&Wlp,  g_Wl);
    cudaGetSymbolAddress((void**)&xshp, g_xsh);
    cudaGetSymbolAddress((void**)&xslp, g_xsl);
    cudaGetSymbolAddress((void**)&xdhp, g_xdh);
    cudaGetSymbolAddress((void**)&xdlp, g_xdl);
    cudaGetSymbolAddress((void**)&Xhp,  g_Xh);
    cudaGetSymbolAddress((void**)&Xlp,  g_Xl);
    cudaGetSymbolAddress((void**)&Yhp,  g_Yh);
    cudaGetSymbolAddress((void**)&Ylp,  g_Yl);
    cudaGetSymbolAddress((void**)&Z1p,  g_Z1);
    cudaGetSymbolAddress((void**)&T1p,  g_T1);
    cudaGetSymbolAddress((void**)&Z2p,  g_Z2);

    auto SPL = [](const float* x, __nv_bfloat16* h, __nv_bfloat16* l, int n) {
        int n4 = n / 4;
        k_split<<<(n4 + 255) / 256, 256>>>((const float4*)x, h, l, n4);
    };

    // Launch order puts a real GEMM at launch #6 so ncu (-s 5 -c 1) captures it.
    SPL(x_src, xshp, xslp, NSRC * INS);                              // 1
    SPL(W_src, Whp + O_WSRC, Wlp + O_WSRC, HIDD * INS);              // 2
    k_mgemm<<<dim3(HIDD / 128, (NSRC + 127) / 128), 256, TG_SMEM>>>( // 3
        xshp, xslp, Whp + O_WSRC, Wlp + O_WSRC, b_src,
        nullptr, Xhp, Xlp, NSRC, HIDD, INS);
    SPL(x_dst, xdhp, xdlp, NDST * IND);                              // 4
    SPL(W_dst, Whp + O_WDST, Wlp + O_WDST, HIDD * IND);              // 5
    k_mgemm<<<dim3(HIDD / 128, (NDST + 127) / 128), 256, TG_SMEM>>>( // 6 <- ncu
        xdhp, xdlp, Whp + O_WDST, Wlp + O_WDST, b_dst,
        nullptr, Xhp + (size_t)NSRC * HIDD, Xlp + (size_t)NSRC * HIDD, NDST, HIDD, IND);

    // remaining weight splits
    SPL(W1l, Whp + O_W1L, Wlp + O_W1L, HIDD * HIDD);
    SPL(W1r, Whp + O_W1R, Wlp + O_W1R, HIDD * HIDD);
    SPL(W2l, Whp + O_W2L, Wlp + O_W2L, OUTD * HIDD);
    SPL(W2r, Whp + O_W2R, Wlp + O_W2R, OUTD * HIDD);

    // edge canonicalization + CSR build
    k_detect<<<1, 1>>>(ei);
    k_convert<<<(2 * NEDGE + 255) / 256, 256>>>(ei);
    k_zero<<<(NDST + 255) / 256, 256>>>();
    k_hist<<<(NEDGE + 255) / 256, 256>>>();
    k_scan<<<1, 1024>>>();
    k_fill<<<(NEDGE + 255) / 256, 256>>>();

    // layer 1: Z1 = X[:10k] @ W1l.T ; T1 = X @ W1r.T + b1 ; T1[dst] += mean(Z1[src])
    k_mgemm<<<dim3(HIDD / 128, (NSRC + 127) / 128), 256, TG_SMEM>>>(
        Xhp, Xlp, Whp + O_W1L, Wlp + O_W1L, nullptr,
        Z1p, nullptr, nullptr, NSRC, HIDD, HIDD);
    k_mgemm<<<dim3(HIDD / 128, (NTOT + 127) / 128), 256, TG_SMEM>>>(
        Xhp, Xlp, Whp + O_W1R, Wlp + O_W1R, b1,
        T1p, nullptr, nullptr, NTOT, HIDD, HIDD);
    k_agg<<<NDST, HIDD / 4>>>(Z1p, T1p + (size_t)NSRC * HIDD);

    // BatchNorm + ReLU -> bf16 split Y
    k_bnstats<<<256, HIDD / 4>>>(T1p);
    k_bncoef<<<1, HIDD>>>(gamma, beta);
    k_bnapply<<<(NTOT * (HIDD / 4) + 255) / 256, 256>>>(T1p, Yhp, Ylp);

    // layer 2: Z2 = Y[:10k] @ W2l.T ; OUT = Y @ W2r.T + b2 ; OUT[dst] += mean(Z2[src])
    k_mgemm<<<dim3(OUTD / 128, (NSRC + 127) / 128), 256, TG_SMEM>>>(
        Yhp, Ylp, Whp + O_W2L, Wlp + O_W2L, nullptr,
        Z2p, nullptr, nullptr, NSRC, OUTD, HIDD);
    k_mgemm<<<dim3(OUTD / 128, (NTOT + 127) / 128), 256, TG_SMEM>>>(
        Yhp, Ylp, Whp + O_W2R, Wlp + O_W2R, b2,
        out, nullptr, nullptr, NTOT, OUTD, HIDD);
    k_agg<<<NDST, OUTD / 4>>>(Z2p, out + (size_t)NSRC * OUTD);
}

// round 10
// speedup vs baseline: 2.2359x; 1.1211x over previous
#include <cuda_runtime.h>
#include <cuda_bf16.h>
#include <cstdint>

// Problem constants (fixed shapes per reference)
#define NSRC  10000
#define NDST  10000
#define NTOT  20000
#define INS   512
#define IND   256
#define HIDD  512
#define OUTD  256
#define NEDGE 160000
#define EPSB  1e-5f

// ---------------------------------------------------------------------------
// PTX helpers — sm_80-baseline only (harness compiles via compute_103
// virtual arch: tcgen05/TMEM unavailable).
// ---------------------------------------------------------------------------
#define SWZ64(o) ((o) ^ (((o) >> 3) & 0x30))   // 64B-row swizzle (8x64B atom)

__device__ __forceinline__ uint32_t smem_to_u32(const void* p) {
    uint32_t a;
    asm("{ .reg .u64 t; cvta.to.shared.u64 t, %1; cvt.u32.u64 %0, t; }"
        : "=r"(a) : "l"(p));
    return a;
}

#define CP16(dst, src) \
    asm volatile("cp.async.cg.shared.global [%0], [%1], 16;" \
                 :: "r"(dst), "l"(src) : "memory")
#define CP_COMMIT() asm volatile("cp.async.commit_group;" ::: "memory")
#define CP_WAIT1()  asm volatile("cp.async.wait_group 1;" ::: "memory")
#define CP_WAIT0()  asm volatile("cp.async.wait_group 0;" ::: "memory")

#define LDSM4(r, addr) \
    asm volatile("ldmatrix.sync.aligned.m8n8.x4.shared.b16 {%0,%1,%2,%3}, [%4];" \
                 : "=r"((r)[0]), "=r"((r)[1]), "=r"((r)[2]), "=r"((r)[3]) \
                 : "r"(addr))

#define MMA16816(d, a, b) \
    asm volatile("mma.sync.aligned.m16n8k16.row.col.f32.bf16.bf16.f32 " \
                 "{%0,%1,%2,%3}, {%4,%5,%6,%7}, {%8,%9}, {%0,%1,%2,%3};" \
                 : "+f"((d)[0]), "+f"((d)[1]), "+f"((d)[2]), "+f"((d)[3]) \
                 : "r"((a)[0]), "r"((a)[1]), "r"((a)[2]), "r"((a)[3]), \
                   "r"((b)[0]), "r"((b)[1]))

// ---------------------------------------------------------------------------
// Scratch (static __device__ — no allocations allowed)
// ---------------------------------------------------------------------------
#define O_WSRC 0
#define O_WDST 262144
#define O_W1L  393216
#define O_W1R  655360
#define O_W2L  917504
#define O_W2R  1048576
#define WTOT   1179648

__device__ __align__(16) __nv_bfloat16 g_Wh[WTOT],  g_Wl[WTOT];
__device__ __align__(16) __nv_bfloat16 g_xsh[NSRC * INS], g_xsl[NSRC * INS];
__device__ __align__(16) __nv_bfloat16 g_xdh[NDST * IND], g_xdl[NDST * IND];
__device__ __align__(16) __nv_bfloat16 g_Xh[NTOT * HIDD], g_Xl[NTOT * HIDD];
__device__ __align__(16) __nv_bfloat16 g_Yh[NTOT * HIDD], g_Yl[NTOT * HIDD];
__device__ __align__(16) float g_Z1[NSRC * HIDD];
__device__ __align__(16) float g_T1[NTOT * HIDD];
__device__ __align__(16) float g_Z2[NSRC * OUTD];
__device__ int   g_edges[2 * NEDGE];
__device__ int   g_is64;
__device__ int   g_cnt[NDST];
__device__ int   g_off[NDST];
__device__ int   g_cur[NDST];
__device__ int   g_csr[NEDGE];
__device__ float g_colsum[HIDD];
__device__ float g_colsumsq[HIDD];
__device__ float g_sc[HIDD];
__device__ float g_sh[HIDD];

// ---------------------------------------------------------------------------
// Edge dtype detection + canonicalization (int32 vs int64 edge_index)
// ---------------------------------------------------------------------------
__global__ void k_detect(const void* p) {
    const int* q = (const int*)p;
    int all0 = 1;
    for (int i = 1; i < 64; i += 2)
        if (q[i] != 0) all0 = 0;
    g_is64 = all0;
}
__global__ void k_convert(const void* p) {
    int i = blockIdx.x * blockDim.x + threadIdx.x;
    if (i < 2 * NEDGE)
        g_edges[i] = g_is64 ? (int)((const long long*)p)[i] : ((const int*)p)[i];
}

// ---------------------------------------------------------------------------
// Graph preprocessing: histogram -> scan -> CSR fill
// ---------------------------------------------------------------------------
__global__ void k_zero() {
    int i = blockIdx.x * blockDim.x + threadIdx.x;
    if (i < NDST) g_cnt[i] = 0;
    if (i < HIDD) { g_colsum[i] = 0.f; g_colsumsq[i] = 0.f; }
}
__global__ void k_hist() {
    int i = blockIdx.x * blockDim.x + threadIdx.x;
    if (i < NEDGE) {
        unsigned d = (unsigned)(g_edges[NEDGE + i] - NSRC);
        if (d < NDST) atomicAdd(&g_cnt[d], 1);
    }
}
__global__ void k_scan() {
    __shared__ int part[1024];
    const int PER = 10;
    int t = threadIdx.x, base = t * PER, loc[PER], s = 0;
#pragma unroll
    for (int i = 0; i < PER; i++) {
        int idx = base + i;
        int v = (idx < NDST) ? g_cnt[idx] : 0;
        loc[i] = s; s += v;
    }
    part[t] = s;
    __syncthreads();
    for (int d = 1; d < 1024; d <<= 1) {
        int v = (t >= d) ? part[t - d] : 0;
        __syncthreads();
        part[t] += v;
        __syncthreads();
    }
    int ex = (t == 0) ? 0 : part[t - 1];
#pragma unroll
    for (int i = 0; i < PER; i++) {
        int idx = base + i;
        if (idx < NDST) { int o = ex + loc[i]; g_off[idx] = o; g_cur[idx] = o; }
    }
}
__global__ void k_fill() {
    int i = blockIdx.x * blockDim.x + threadIdx.x;
    if (i < NEDGE) {
        unsigned d = (unsigned)(g_edges[NEDGE + i] - NSRC);
        unsigned s = (unsigned)g_edges[i];
        if (d < NDST && s < NSRC) {
            int p = atomicAdd(&g_cur[d], 1);
            if (p < NEDGE) g_csr[p] = (int)s;
        }
    }
}

// ---------------------------------------------------------------------------
// fp32 -> bf16 (hi, lo) split
// ---------------------------------------------------------------------------
__global__ void k_split(const float4* __restrict__ x,
                        __nv_bfloat16* __restrict__ h,
                        __nv_bfloat16* __restrict__ l, int n4) {
    int i = blockIdx.x * blockDim.x + threadIdx.x;
    if (i >= n4) return;
    float4 v = x[i];
    float f[4] = {v.x, v.y, v.z, v.w};
    __nv_bfloat16 hb[4], lb[4];
#pragma unroll
    for (int j = 0; j < 4; j++) {
        hb[j] = __float2bfloat16(f[j]);
        lb[j] = __float2bfloat16(f[j] - __bfloat162float(hb[j]));
    }
    __nv_bfloat162* hp = (__nv_bfloat162*)h + i * 2;
    __nv_bfloat162* lp = (__nv_bfloat162*)l + i * 2;
    hp[0] = __halves2bfloat162(hb[0], hb[1]);
    hp[1] = __halves2bfloat162(hb[2], hb[3]);
    lp[0] = __halves2bfloat162(lb[0], lb[1]);
    lp[1] = __halves2bfloat162(lb[2], lb[3]);
}

// ---------------------------------------------------------------------------
// Warp-MMA bf16-split GEMM: C[M,N] = (Ah+Al)[M,K] @ (Bh+Bl)[N,K]^T (+ bias)
// 128x128 CTA tile, 8 warps (4M x 2N), warp tile 32x64, m16n8k16 HMMA,
// 3 MMAs per term (hi*hi + hi*lo + lo*hi).
// 3-stage cp.async pipeline (32KB/stage = 96KB) -> 2 CTAs/SM so barrier /
// epilogue bubbles in one CTA are covered by the other CTA's mainloop.
// B fragments loaded per-nj to keep the working set under the 128-reg cap.
// Epilogue writes fp32 (Cf) and/or bf16 split (Ch, Cl).
// ---------------------------------------------------------------------------
#define STG_BYTES 32768
#define TG_SMEM   (3 * STG_BYTES)

__global__ void __launch_bounds__(256, 2) k_mgemm(
    const __nv_bfloat16* __restrict__ Ah, const __nv_bfloat16* __restrict__ Al,
    const __nv_bfloat16* __restrict__ Bh, const __nv_bfloat16* __restrict__ Bl,
    const float* __restrict__ bias,
    float* __restrict__ Cf,
    __nv_bfloat16* __restrict__ Ch, __nv_bfloat16* __restrict__ Cl,
    int M, int N, int K)
{
    extern __shared__ __align__(1024) char smem[];
    const uint32_t smb = smem_to_u32(smem);
    const int tid = threadIdx.x, wid = tid >> 5, lane = tid & 31;
    const int m0 = blockIdx.y * 128, n0 = blockIdx.x * 128;
    const int warp_m = (wid >> 1) * 32;     // 4 warps along M
    const int warp_n = (wid & 1) * 64;      // 2 warps along N

    float acc[2][8][4] = {};

    const int NC = K >> 5;   // K chunks of 32

    // stage layout: Ah @0, Al @8K, Bh @16K, Bl @24K  (64B rows, SW64 swizzle)
    auto load_chunk = [&](int c, int buf) {
        uint32_t bo = smb + (uint32_t)buf * STG_BYTES;
        int k0 = c << 5;
#pragma unroll
        for (int it = 0; it < 2; it++) {
            int seg = tid + it * 256;        // 0..511
            int row = seg >> 2;              // 0..127
            int sg  = seg & 3;               // 16B segment in 64B row
            uint32_t sw = SWZ64((uint32_t)(row * 64 + sg * 16));
            size_t acol = (size_t)(k0 + sg * 8);
            int gm = m0 + row; if (gm >= M) gm = M - 1;   // clamp: never stored
            int gn = n0 + row;
            CP16(bo + sw,         (const char*)(Ah + (size_t)gm * K + acol));
            CP16(bo + 8192  + sw, (const char*)(Al + (size_t)gm * K + acol));
            CP16(bo + 16384 + sw, (const char*)(Bh + (size_t)gn * K + acol));
            CP16(bo + 24576 + sw, (const char*)(Bl + (size_t)gn * K + acol));
        }
        CP_COMMIT();
    };

    load_chunk(0, 0);
    if (NC > 1) load_chunk(1, 1);

    const int q  = lane >> 3;   // ldmatrix sub-matrix index
    const int rr = lane & 7;

    // 3-stage: buffers cycle mod 3; prefetch distance 2.
    int buf_c = 0;
    for (int c = 0; c < NC; c++) {
        if (c + 1 < NC) CP_WAIT1(); else CP_WAIT0();
        __syncthreads();                        // chunk-c visible; buf of c-1 free
        if (c + 2 < NC) {
            int nb = buf_c + 2; if (nb >= 3) nb -= 3;
            load_chunk(c + 2, nb);
        }

        uint32_t bo = smb + (uint32_t)buf_c * STG_BYTES;
#pragma unroll
        for (int ks = 0; ks < 2; ks++) {
            const uint32_t kb = (uint32_t)(ks * 32 + (q >> 1) * 16);
            uint32_t ahf[2][4], alf[2][4];
#pragma unroll
            for (int mi = 0; mi < 2; mi++) {
                uint32_t arow = (uint32_t)(warp_m + mi * 16 + (q & 1) * 8 + rr);
                uint32_t ad = bo + SWZ64(arow * 64 + kb);
                LDSM4(ahf[mi], ad);
                LDSM4(alf[mi], ad + 8192);
            }
#pragma unroll
            for (int nj = 0; nj < 4; nj++) {
                uint32_t bhf[4], blf[4];
                uint32_t brow = (uint32_t)(warp_n + nj * 16 + (q & 1) * 8 + rr);
                uint32_t bd = bo + 16384 + SWZ64(brow * 64 + kb);
                LDSM4(bhf, bd);
                LDSM4(blf, bd + 8192);
#pragma unroll
                for (int mi = 0; mi < 2; mi++)
#pragma unroll
                    for (int sub = 0; sub < 2; sub++) {
                        const int ni = nj * 2 + sub;
                        uint32_t bh2[2] = { bhf[sub], bhf[sub + 2] };
                        uint32_t bl2[2] = { blf[sub], blf[sub + 2] };
                        MMA16816(acc[mi][ni], ahf[mi], bh2);   // hi*hi
                        MMA16816(acc[mi][ni], ahf[mi], bl2);   // hi*lo
                        MMA16816(acc[mi][ni], alf[mi], bh2);   // lo*hi
                    }
            }
        }
        if (++buf_c == 3) buf_c = 0;
    }

    // --- epilogue ---
#pragma unroll
    for (int mi = 0; mi < 2; mi++) {
        int mrow = m0 + warp_m + mi * 16 + (lane >> 2);
#pragma unroll
        for (int half = 0; half < 2; half++) {
            int gm = mrow + half * 8;
            if (gm < M) {
#pragma unroll
                for (int ni = 0; ni < 8; ni++) {
                    int gn = n0 + warp_n + ni * 8 + (lane & 3) * 2;
                    float v0 = acc[mi][ni][half * 2 + 0];
                    float v1 = acc[mi][ni][half * 2 + 1];
                    if (bias) { v0 += bias[gn]; v1 += bias[gn + 1]; }
                    size_t o = (size_t)gm * N + gn;
                    if (Cf) *(float2*)(Cf + o) = make_float2(v0, v1);
                    if (Ch) {
                        __nv_bfloat16 h0 = __float2bfloat16(v0);
                        __nv_bfloat16 h1 = __float2bfloat16(v1);
                        *(__nv_bfloat162*)(Ch + o) = __halves2bfloat162(h0, h1);
                        *(__nv_bfloat162*)(Cl + o) = __halves2bfloat162(
                            __float2bfloat16(v0 - __bfloat162float(h0)),
                            __float2bfloat16(v1 - __bfloat162float(h1)));
                    }
                }
            }
        }
    }
}

// ---------------------------------------------------------------------------
// CSR aggregation: C[d] += mean_{s in nbrs(d)} Z[s]   (2-deep unroll)
// ---------------------------------------------------------------------------
__global__ void k_agg(const float* __restrict__ Z, float* __restrict__ C) {
    int d = blockIdx.x;
    int deg = g_cnt[d];
    if (deg == 0) return;
    int W4 = blockDim.x;
    const float4* Z4 = (const float4*)Z;
    float4 acc = make_float4(0.f, 0.f, 0.f, 0.f);
    int o = g_off[d];
    int e = 0;
    for (; e + 2 <= deg; e += 2) {
        int s0 = g_csr[o + e], s1 = g_csr[o + e + 1];
        float4 v0 = Z4[(size_t)s0 * W4 + threadIdx.x];
        float4 v1 = Z4[(size_t)s1 * W4 + threadIdx.x];
        acc.x += v0.x + v1.x; acc.y += v0.y + v1.y;
        acc.z += v0.z + v1.z; acc.w += v0.w + v1.w;
    }
    if (e < deg) {
        int s = g_csr[o + e];
        float4 v = Z4[(size_t)s * W4 + threadIdx.x];
        acc.x += v.x; acc.y += v.y; acc.z += v.z; acc.w += v.w;
    }
    float inv = 1.0f / (float)deg;
    float4* C4 = (float4*)C;
    size_t oi = (size_t)d * W4 + threadIdx.x;
    float4 c = C4[oi];
    c.x += acc.x * inv; c.y += acc.y * inv;
    c.z += acc.z * inv; c.w += acc.w * inv;
    C4[oi] = c;
}

// ---------------------------------------------------------------------------
// BatchNorm (training stats) + ReLU; apply writes bf16 hi/lo for layer 2
// ---------------------------------------------------------------------------
__global__ void k_bnstats(const float* __restrict__ T) {
    const float4* T4 = (const float4*)T;
    float4 s = make_float4(0.f, 0.f, 0.f, 0.f);
    float4 q = make_float4(0.f, 0.f, 0.f, 0.f);
    for (int r = blockIdx.x; r < NTOT; r += gridDim.x) {
        float4 v = T4[(size_t)r * (HIDD / 4) + threadIdx.x];
        s.x += v.x; s.y += v.y; s.z += v.z; s.w += v.w;
        q.x += v.x * v.x; q.y += v.y * v.y; q.z += v.z * v.z; q.w += v.w * v.w;
    }
    int c = threadIdx.x * 4;
    atomicAdd(&g_colsum[c + 0], s.x); atomicAdd(&g_colsum[c + 1], s.y);
    atomicAdd(&g_colsum[c + 2], s.z); atomicAdd(&g_colsum[c + 3], s.w);
    atomicAdd(&g_colsumsq[c + 0], q.x); atomicAdd(&g_colsumsq[c + 1], q.y);
    atomicAdd(&g_colsumsq[c + 2], q.z); atomicAdd(&g_colsumsq[c + 3], q.w);
}
__global__ void k_bncoef(const float* __restrict__ gamma,
                         const float* __restrict__ beta) {
    int c = threadIdx.x;
    if (c < HIDD) {
        float mu  = g_colsum[c]   * (1.0f / NTOT);
        float var = g_colsumsq[c] * (1.0f / NTOT) - mu * mu;
        float s = gamma[c] * rsqrtf(var + EPSB);
        g_sc[c] = s;
        g_sh[c] = beta[c] - mu * s;
    }
}
__global__ void k_bnapply(const float* __restrict__ T,
                          __nv_bfloat16* __restrict__ Yh,
                          __nv_bfloat16* __restrict__ Yl) {
    int idx = blockIdx.x * blockDim.x + threadIdx.x;   // float4 index
    const int TOT4 = NTOT * (HIDD / 4);
    if (idx >= TOT4) return;
    int c4 = idx & (HIDD / 4 - 1);
    float4 v = ((const float4*)T)[idx];
    float4 s = ((const float4*)g_sc)[c4];
    float4 h = ((const float4*)g_sh)[c4];
    float f[4];
    f[0] = fmaxf(fmaf(v.x, s.x, h.x), 0.f);
    f[1] = fmaxf(fmaf(v.y, s.y, h.y), 0.f);
    f[2] = fmaxf(fmaf(v.z, s.z, h.z), 0.f);
    f[3] = fmaxf(fmaf(v.w, s.w, h.w), 0.f);
    __nv_bfloat16 hb[4], lb[4];
#pragma unroll
    for (int j = 0; j < 4; j++) {
        hb[j] = __float2bfloat16(f[j]);
        lb[j] = __float2bfloat16(f[j] - __bfloat162float(hb[j]));
    }
    __nv_bfloat162* hp = (__nv_bfloat162*)Yh + idx * 2;
    __nv_bfloat162* lp = (__nv_bfloat162*)Yl + idx * 2;
    hp[0] = __halves2bfloat162(hb[0], hb[1]);
    hp[1] = __halves2bfloat162(hb[2], hb[3]);
    lp[0] = __halves2bfloat162(lb[0], lb[1]);
    lp[1] = __halves2bfloat162(lb[2], lb[3]);
}

// ---------------------------------------------------------------------------
// Launch
// ---------------------------------------------------------------------------
extern "C" void kernel_launch(void* const* d_in, const int* in_sizes, int n_in,
                              void* d_out, int out_size) {
    const float* x_src = (const float*)d_in[0];
    const float* x_dst = (const float*)d_in[1];
    const float* W_src = (const float*)d_in[2];
    const float* b_src = (const float*)d_in[3];
    const float* W_dst = (const float*)d_in[4];
    const float* b_dst = (const float*)d_in[5];
    const float* W1l   = (const float*)d_in[6];
    const float* b1    = (const float*)d_in[7];
    const float* W1r   = (const float*)d_in[8];
    const float* W2l   = (const float*)d_in[9];
    const float* b2    = (const float*)d_in[10];
    const float* W2r   = (const float*)d_in[11];
    const float* gamma = (const float*)d_in[12];
    const float* beta  = (const float*)d_in[13];
    const void*  ei    = d_in[14];
    float* out = (float*)d_out;

    static int attr_set = 0;
    if (!attr_set) {
        cudaFuncSetAttribute(k_mgemm, cudaFuncAttributeMaxDynamicSharedMemorySize, TG_SMEM);
        attr_set = 1;
    }

    __nv_bfloat16 *Whp, *Wlp, *xshp, *xslp, *xdhp, *xdlp, *Xhp, *Xlp, *Yhp, *Ylp;
    float *Z1p, *T1p, *Z2p;
    cudaGetSymbolAddress((void**)&Whp,  g_Wh);
    cudaGetSymbolAddress((void**)&Wlp,  g_Wl);
    cudaGetSymbolAddress((void**)&xshp, g_xsh);
    cudaGetSymbolAddress((void**)&xslp, g_xsl);
    cudaGetSymbolAddress((void**)&xdhp, g_xdh);
    cudaGetSymbolAddress((void**)&xdlp, g_xdl);
    cudaGetSymbolAddress((void**)&Xhp,  g_Xh);
    cudaGetSymbolAddress((void**)&Xlp,  g_Xl);
    cudaGetSymbolAddress((void**)&Yhp,  g_Yh);
    cudaGetSymbolAddress((void**)&Ylp,  g_Yl);
    cudaGetSymbolAddress((void**)&Z1p,  g_Z1);
    cudaGetSymbolAddress((void**)&T1p,  g_T1);
    cudaGetSymbolAddress((void**)&Z2p,  g_Z2);

    auto SPL = [](const float* x, __nv_bfloat16* h, __nv_bfloat16* l, int n) {
        int n4 = n / 4;
        k_split<<<(n4 + 255) / 256, 256>>>((const float4*)x, h, l, n4);
    };

    // Launch order keeps a real GEMM near slot #6 for ncu (-s 5 -c 1).
    SPL(x_src, xshp, xslp, NSRC * INS);                              // 1
    SPL(W_src, Whp + O_WSRC, Wlp + O_WSRC, HIDD * INS);              // 2
    k_mgemm<<<dim3(HIDD / 128, (NSRC + 127) / 128), 256, TG_SMEM>>>( // 3
        xshp, xslp, Whp + O_WSRC, Wlp + O_WSRC, b_src,
        nullptr, Xhp, Xlp, NSRC, HIDD, INS);
    SPL(x_dst, xdhp, xdlp, NDST * IND);                              // 4
    SPL(W_dst, Whp + O_WDST, Wlp + O_WDST, HIDD * IND);              // 5
    k_mgemm<<<dim3(HIDD / 128, (NDST + 127) / 128), 256, TG_SMEM>>>( // 6 <- ncu
        xdhp, xdlp, Whp + O_WDST, Wlp + O_WDST, b_dst,
        nullptr, Xhp + (size_t)NSRC * HIDD, Xlp + (size_t)NSRC * HIDD, NDST, HIDD, IND);

    // remaining weight splits
    SPL(W1l, Whp + O_W1L, Wlp + O_W1L, HIDD * HIDD);
    SPL(W1r, Whp + O_W1R, Wlp + O_W1R, HIDD * HIDD);
    SPL(W2l, Whp + O_W2L, Wlp + O_W2L, OUTD * HIDD);
    SPL(W2r, Whp + O_W2R, Wlp + O_W2R, OUTD * HIDD);

    // edge canonicalization + CSR build
    k_detect<<<1, 1>>>(ei);
    k_convert<<<(2 * NEDGE + 255) / 256, 256>>>(ei);
    k_zero<<<(NDST + 255) / 256, 256>>>();
    k_hist<<<(NEDGE + 255) / 256, 256>>>();
    k_scan<<<1, 1024>>>();
    k_fill<<<(NEDGE + 255) / 256, 256>>>();

    // layer 1: Z1 = X[:10k] @ W1l.T ; T1 = X @ W1r.T + b1 ; T1[dst] += mean(Z1[src])
    k_mgemm<<<dim3(HIDD / 128, (NSRC + 127) / 128), 256, TG_SMEM>>>(
        Xhp, Xlp, Whp + O_W1L, Wlp + O_W1L, nullptr,
        Z1p, nullptr, nullptr, NSRC, HIDD, HIDD);
    k_mgemm<<<dim3(HIDD / 128, (NTOT + 127) / 128), 256, TG_SMEM>>>(
        Xhp, Xlp, Whp + O_W1R, Wlp + O_W1R, b1,
        T1p, nullptr, nullptr, NTOT, HIDD, HIDD);
    k_agg<<<NDST, HIDD / 4>>>(Z1p, T1p + (size_t)NSRC * HIDD);

    // BatchNorm + ReLU -> bf16 split Y
    k_bnstats<<<256, HIDD / 4>>>(T1p);
    k_bncoef<<<1, HIDD>>>(gamma, beta);
    k_bnapply<<<(NTOT * (HIDD / 4) + 255) / 256, 256>>>(T1p, Yhp, Ylp);

    // layer 2: Z2 = Y[:10k] @ W2l.T ; OUT = Y @ W2r.T + b2 ; OUT[dst] += mean(Z2[src])
    k_mgemm<<<dim3(OUTD / 128, (NSRC + 127) / 128), 256, TG_SMEM>>>(
        Yhp, Ylp, Whp + O_W2L, Wlp + O_W2L, nullptr,
        Z2p, nullptr, nullptr, NSRC, OUTD, HIDD);
    k_mgemm<<<dim3(OUTD / 128, (NTOT + 127) / 128), 256, TG_SMEM>>>(
        Yhp, Ylp, Whp + O_W2R, Wlp + O_W2R, b2,
        out, nullptr, nullptr, NTOT, OUTD, HIDD);
    k_agg<<<NDST, OUTD / 4>>>(Z2p, out + (size_t)NSRC * OUTD);
}

// round 11
// speedup vs baseline: 2.6719x; 1.1950x over previous
#include <cuda_runtime.h>
#include <cuda_bf16.h>
#include <cstdint>

// Problem constants (fixed shapes per reference)
#define NSRC  10000
#define NDST  10000
#define NTOT  20000
#define INS   512
#define IND   256
#define HIDD  512
#define OUTD  256
#define NEDGE 160000
#define EPSB  1e-5f

// ---------------------------------------------------------------------------
// PTX helpers — sm_80-baseline only (harness compiles via compute_103
// virtual arch: tcgen05/TMEM unavailable).
// ---------------------------------------------------------------------------
#define SWZ64(o) ((o) ^ (((o) >> 3) & 0x30))   // 64B-row swizzle (8x64B atom)

__device__ __forceinline__ uint32_t smem_to_u32(const void* p) {
    uint32_t a;
    asm("{ .reg .u64 t; cvta.to.shared.u64 t, %1; cvt.u32.u64 %0, t; }"
        : "=r"(a) : "l"(p));
    return a;
}

#define CP16(dst, src) \
    asm volatile("cp.async.cg.shared.global [%0], [%1], 16;" \
                 :: "r"(dst), "l"(src) : "memory")
#define CP_COMMIT() asm volatile("cp.async.commit_group;" ::: "memory")
#define CP_WAIT1()  asm volatile("cp.async.wait_group 1;" ::: "memory")
#define CP_WAIT0()  asm volatile("cp.async.wait_group 0;" ::: "memory")

#define LDSM4(r, addr) \
    asm volatile("ldmatrix.sync.aligned.m8n8.x4.shared.b16 {%0,%1,%2,%3}, [%4];" \
                 : "=r"((r)[0]), "=r"((r)[1]), "=r"((r)[2]), "=r"((r)[3]) \
                 : "r"(addr))

#define MMA16816(d, a, b) \
    asm volatile("mma.sync.aligned.m16n8k16.row.col.f32.bf16.bf16.f32 " \
                 "{%0,%1,%2,%3}, {%4,%5,%6,%7}, {%8,%9}, {%0,%1,%2,%3};" \
                 : "+f"((d)[0]), "+f"((d)[1]), "+f"((d)[2]), "+f"((d)[3]) \
                 : "r"((a)[0]), "r"((a)[1]), "r"((a)[2]), "r"((a)[3]), \
                   "r"((b)[0]), "r"((b)[1]))

// ---------------------------------------------------------------------------
// Scratch (static __device__ — no allocations allowed)
// ---------------------------------------------------------------------------
#define O_WSRC 0
#define O_WDST 262144
#define O_W1L  393216
#define O_W1R  655360
#define O_W2L  917504
#define O_W2R  1048576
#define WTOT   1179648

__device__ __align__(16) __nv_bfloat16 g_Wh[WTOT],  g_Wl[WTOT];
__device__ __align__(16) __nv_bfloat16 g_xsh[NSRC * INS], g_xsl[NSRC * INS];
__device__ __align__(16) __nv_bfloat16 g_xdh[NDST * IND], g_xdl[NDST * IND];
__device__ __align__(16) __nv_bfloat16 g_Xh[NTOT * HIDD], g_Xl[NTOT * HIDD];
__device__ __align__(16) __nv_bfloat16 g_Yh[NTOT * HIDD], g_Yl[NTOT * HIDD];
__device__ __align__(16) float g_Z1[NSRC * HIDD];
__device__ __align__(16) float g_T1[NTOT * HIDD];
__device__ __align__(16) float g_Z2[NSRC * OUTD];
__device__ int   g_edges[2 * NEDGE];
__device__ int   g_cnt[NDST];
__device__ int   g_off[NDST];
__device__ int   g_cur[NDST];
__device__ int   g_csr[NEDGE];
__device__ float g_colsum[HIDD];
__device__ float g_colsumsq[HIDD];
__device__ float g_sc[HIDD];
__device__ float g_sh[HIDD];

// ---------------------------------------------------------------------------
// k_prep: edge dtype detect (per-block, warp ballot) + convert + zero buffers
// JAX with x64 disabled silently stores edge_index as int32; handle both.
// ---------------------------------------------------------------------------
__global__ void k_prep(const void* p) {
    __shared__ int s_is64;
    if (threadIdx.x < 32) {
        const int* q = (const int*)p;
        int v = q[threadIdx.x * 2 + 1];
        unsigned m = __ballot_sync(0xffffffff, v != 0);
        if (threadIdx.x == 0) s_is64 = (m == 0);
    }
    __syncthreads();
    int is64 = s_is64;
    int i = blockIdx.x * blockDim.x + threadIdx.x;
    if (i < 2 * NEDGE)
        g_edges[i] = is64 ? (int)((const long long*)p)[i] : ((const int*)p)[i];
    if (i < NDST) g_cnt[i] = 0;
    if (i < HIDD) { g_colsum[i] = 0.f; g_colsumsq[i] = 0.f; }
}

// ---------------------------------------------------------------------------
// Graph preprocessing: histogram -> scan -> CSR fill
// ---------------------------------------------------------------------------
__global__ void k_hist() {
    int i = blockIdx.x * blockDim.x + threadIdx.x;
    if (i < NEDGE) {
        unsigned d = (unsigned)(g_edges[NEDGE + i] - NSRC);
        if (d < NDST) atomicAdd(&g_cnt[d], 1);
    }
}
__global__ void k_scan() {
    __shared__ int part[1024];
    const int PER = 10;
    int t = threadIdx.x, base = t * PER, loc[PER], s = 0;
#pragma unroll
    for (int i = 0; i < PER; i++) {
        int idx = base + i;
        int v = (idx < NDST) ? g_cnt[idx] : 0;
        loc[i] = s; s += v;
    }
    part[t] = s;
    __syncthreads();
    for (int d = 1; d < 1024; d <<= 1) {
        int v = (t >= d) ? part[t - d] : 0;
        __syncthreads();
        part[t] += v;
        __syncthreads();
    }
    int ex = (t == 0) ? 0 : part[t - 1];
#pragma unroll
    for (int i = 0; i < PER; i++) {
        int idx = base + i;
        if (idx < NDST) { int o = ex + loc[i]; g_off[idx] = o; g_cur[idx] = o; }
    }
}
__global__ void k_fill() {
    int i = blockIdx.x * blockDim.x + threadIdx.x;
    if (i < NEDGE) {
        unsigned d = (unsigned)(g_edges[NEDGE + i] - NSRC);
        unsigned s = (unsigned)g_edges[i];
        if (d < NDST && s < NSRC) {
            int p = atomicAdd(&g_cur[d], 1);
            if (p < NEDGE) g_csr[p] = (int)s;
        }
    }
}

// ---------------------------------------------------------------------------
// Fused fp32 -> bf16 (hi, lo) split over 8 arrays in ONE launch
// ---------------------------------------------------------------------------
struct SplitJobs {
    const float4* src[8];
    __nv_bfloat16* h[8];
    __nv_bfloat16* l[8];
    int n4[8];
    int nblk[8];
};

__global__ void k_split8(SplitJobs j) {
    int b = blockIdx.x;
    int seg = 0;
#pragma unroll
    for (int s = 0; s < 7; s++)
        if (b >= j.nblk[seg]) { b -= j.nblk[seg]; seg++; }
    int i = b * blockDim.x + threadIdx.x;
    if (i >= j.n4[seg]) return;
    float4 v = j.src[seg][i];
    float f[4] = {v.x, v.y, v.z, v.w};
    __nv_bfloat16 hb[4], lb[4];
#pragma unroll
    for (int k = 0; k < 4; k++) {
        hb[k] = __float2bfloat16(f[k]);
        lb[k] = __float2bfloat16(f[k] - __bfloat162float(hb[k]));
    }
    __nv_bfloat162* hp = (__nv_bfloat162*)j.h[seg] + i * 2;
    __nv_bfloat162* lp = (__nv_bfloat162*)j.l[seg] + i * 2;
    hp[0] = __halves2bfloat162(hb[0], hb[1]);
    hp[1] = __halves2bfloat162(hb[2], hb[3]);
    lp[0] = __halves2bfloat162(lb[0], lb[1]);
    lp[1] = __halves2bfloat162(lb[2], lb[3]);
}

// ---------------------------------------------------------------------------
// Warp-MMA bf16-split GEMM body: C[M,N] = (Ah+Al)[M,K] @ (Bh+Bl)[N,K]^T (+bias)
// 128x128 tile, 8 warps (4M x 2N), warp tile 32x64, m16n8k16 HMMA,
// 3 MMAs per term (hi*hi + hi*lo + lo*hi).
// 3-stage cp.async pipeline (32KB/stage = 96KB) -> 2 CTAs/SM.
// ---------------------------------------------------------------------------
#define STG_BYTES 32768
#define TG_SMEM   (3 * STG_BYTES)

__device__ __forceinline__ void mgemm_body(
    const __nv_bfloat16* __restrict__ Ah, const __nv_bfloat16* __restrict__ Al,
    const __nv_bfloat16* __restrict__ Bh, const __nv_bfloat16* __restrict__ Bl,
    const float* __restrict__ bias,
    float* __restrict__ Cf,
    __nv_bfloat16* __restrict__ Ch, __nv_bfloat16* __restrict__ Cl,
    int M, int N, int K, int m0, int n0)
{
    extern __shared__ __align__(1024) char smem[];
    const uint32_t smb = smem_to_u32(smem);
    const int tid = threadIdx.x, wid = tid >> 5, lane = tid & 31;
    const int warp_m = (wid >> 1) * 32;     // 4 warps along M
    const int warp_n = (wid & 1) * 64;      // 2 warps along N

    float acc[2][8][4] = {};

    const int NC = K >> 5;   // K chunks of 32

    // stage layout: Ah @0, Al @8K, Bh @16K, Bl @24K  (64B rows, SW64 swizzle)
    auto load_chunk = [&](int c, int buf) {
        uint32_t bo = smb + (uint32_t)buf * STG_BYTES;
        int k0 = c << 5;
#pragma unroll
        for (int it = 0; it < 2; it++) {
            int seg = tid + it * 256;        // 0..511
            int row = seg >> 2;              // 0..127
            int sg  = seg & 3;               // 16B segment in 64B row
            uint32_t sw = SWZ64((uint32_t)(row * 64 + sg * 16));
            size_t acol = (size_t)(k0 + sg * 8);
            int gm = m0 + row; if (gm >= M) gm = M - 1;   // clamp: never stored
            int gn = n0 + row;
            CP16(bo + sw,         (const char*)(Ah + (size_t)gm * K + acol));
            CP16(bo + 8192  + sw, (const char*)(Al + (size_t)gm * K + acol));
            CP16(bo + 16384 + sw, (const char*)(Bh + (size_t)gn * K + acol));
            CP16(bo + 24576 + sw, (const char*)(Bl + (size_t)gn * K + acol));
        }
        CP_COMMIT();
    };

    load_chunk(0, 0);
    if (NC > 1) load_chunk(1, 1);

    const int q  = lane >> 3;   // ldmatrix sub-matrix index
    const int rr = lane & 7;

    int buf_c = 0;
    for (int c = 0; c < NC; c++) {
        if (c + 1 < NC) CP_WAIT1(); else CP_WAIT0();
        __syncthreads();                        // chunk-c visible; buf of c-1 free
        if (c + 2 < NC) {
            int nb = buf_c + 2; if (nb >= 3) nb -= 3;
            load_chunk(c + 2, nb);
        }

        uint32_t bo = smb + (uint32_t)buf_c * STG_BYTES;
#pragma unroll
        for (int ks = 0; ks < 2; ks++) {
            const uint32_t kb = (uint32_t)(ks * 32 + (q >> 1) * 16);
            uint32_t ahf[2][4], alf[2][4];
#pragma unroll
            for (int mi = 0; mi < 2; mi++) {
                uint32_t arow = (uint32_t)(warp_m + mi * 16 + (q & 1) * 8 + rr);
                uint32_t ad = bo + SWZ64(arow * 64 + kb);
                LDSM4(ahf[mi], ad);
                LDSM4(alf[mi], ad + 8192);
            }
#pragma unroll
            for (int nj = 0; nj < 4; nj++) {
                uint32_t bhf[4], blf[4];
                uint32_t brow = (uint32_t)(warp_n + nj * 16 + (q & 1) * 8 + rr);
                uint32_t bd = bo + 16384 + SWZ64(brow * 64 + kb);
                LDSM4(bhf, bd);
                LDSM4(blf, bd + 8192);
#pragma unroll
                for (int mi = 0; mi < 2; mi++)
#pragma unroll
                    for (int sub = 0; sub < 2; sub++) {
                        const int ni = nj * 2 + sub;
                        uint32_t bh2[2] = { bhf[sub], bhf[sub + 2] };
                        uint32_t bl2[2] = { blf[sub], blf[sub + 2] };
                        MMA16816(acc[mi][ni], ahf[mi], bh2);   // hi*hi
                        MMA16816(acc[mi][ni], ahf[mi], bl2);   // hi*lo
                        MMA16816(acc[mi][ni], alf[mi], bh2);   // lo*hi
                    }
            }
        }
        if (++buf_c == 3) buf_c = 0;
    }

    // --- epilogue ---
#pragma unroll
    for (int mi = 0; mi < 2; mi++) {
        int mrow = m0 + warp_m + mi * 16 + (lane >> 2);
#pragma unroll
        for (int half = 0; half < 2; half++) {
            int gm = mrow + half * 8;
            if (gm < M) {
#pragma unroll
                for (int ni = 0; ni < 8; ni++) {
                    int gn = n0 + warp_n + ni * 8 + (lane & 3) * 2;
                    float v0 = acc[mi][ni][half * 2 + 0];
                    float v1 = acc[mi][ni][half * 2 + 1];
                    if (bias) { v0 += bias[gn]; v1 += bias[gn + 1]; }
                    size_t o = (size_t)gm * N + gn;
                    if (Cf) *(float2*)(Cf + o) = make_float2(v0, v1);
                    if (Ch) {
                        __nv_bfloat16 h0 = __float2bfloat16(v0);
                        __nv_bfloat16 h1 = __float2bfloat16(v1);
                        *(__nv_bfloat162*)(Ch + o) = __halves2bfloat162(h0, h1);
                        *(__nv_bfloat162*)(Cl + o) = __halves2bfloat162(
                            __float2bfloat16(v0 - __bfloat162float(h0)),
                            __float2bfloat16(v1 - __bfloat162float(h1)));
                    }
                }
            }
        }
    }
}

// ---------------------------------------------------------------------------
// Dual-GEMM launch: grid covers two independent GEMMs so the block scheduler
// backfills GEMM0's tail wave with GEMM1's head blocks (kills wave quant).
// ---------------------------------------------------------------------------
struct GArgs {
    const __nv_bfloat16 *Ah, *Al, *Bh, *Bl;
    const float* bias;
    float* Cf;
    __nv_bfloat16 *Ch, *Cl;
    int M, N, K;
    int nblk, nbx;
};

__global__ void __launch_bounds__(256, 2) k_mgemm2(GArgs a0, GArgs a1) {
    int b = blockIdx.x;
    if (b < a0.nblk) {
        int by = b / a0.nbx, bx = b - by * a0.nbx;
        mgemm_body(a0.Ah, a0.Al, a0.Bh, a0.Bl, a0.bias, a0.Cf, a0.Ch, a0.Cl,
                   a0.M, a0.N, a0.K, by * 128, bx * 128);
    } else {
        b -= a0.nblk;
        int by = b / a1.nbx, bx = b - by * a1.nbx;
        mgemm_body(a1.Ah, a1.Al, a1.Bh, a1.Bl, a1.bias, a1.Cf, a1.Ch, a1.Cl,
                   a1.M, a1.N, a1.K, by * 128, bx * 128);
    }
}

// ---------------------------------------------------------------------------
// CSR aggregation: C[d] += mean_{s in nbrs(d)} Z[s]   (2-deep unroll)
// ---------------------------------------------------------------------------
__global__ void k_agg(const float* __restrict__ Z, float* __restrict__ C) {
    int d = blockIdx.x;
    int deg = g_cnt[d];
    if (deg == 0) return;
    int W4 = blockDim.x;
    const float4* Z4 = (const float4*)Z;
    float4 acc = make_float4(0.f, 0.f, 0.f, 0.f);
    int o = g_off[d];
    int e = 0;
    for (; e + 2 <= deg; e += 2) {
        int s0 = g_csr[o + e], s1 = g_csr[o + e + 1];
        float4 v0 = Z4[(size_t)s0 * W4 + threadIdx.x];
        float4 v1 = Z4[(size_t)s1 * W4 + threadIdx.x];
        acc.x += v0.x + v1.x; acc.y += v0.y + v1.y;
        acc.z += v0.z + v1.z; acc.w += v0.w + v1.w;
    }
    if (e < deg) {
        int s = g_csr[o + e];
        float4 v = Z4[(size_t)s * W4 + threadIdx.x];
        acc.x += v.x; acc.y += v.y; acc.z += v.z; acc.w += v.w;
    }
    float inv = 1.0f / (float)deg;
    float4* C4 = (float4*)C;
    size_t oi = (size_t)d * W4 + threadIdx.x;
    float4 c = C4[oi];
    c.x += acc.x * inv; c.y += acc.y * inv;
    c.z += acc.z * inv; c.w += acc.w * inv;
    C4[oi] = c;
}

// ---------------------------------------------------------------------------
// BatchNorm (training stats) + ReLU; apply writes bf16 hi/lo for layer 2
// ---------------------------------------------------------------------------
__global__ void k_bnstats(const float* __restrict__ T) {
    const float4* T4 = (const float4*)T;
    float4 s = make_float4(0.f, 0.f, 0.f, 0.f);
    float4 q = make_float4(0.f, 0.f, 0.f, 0.f);
    for (int r = blockIdx.x; r < NTOT; r += gridDim.x) {
        float4 v = T4[(size_t)r * (HIDD / 4) + threadIdx.x];
        s.x += v.x; s.y += v.y; s.z += v.z; s.w += v.w;
        q.x += v.x * v.x; q.y += v.y * v.y; q.z += v.z * v.z; q.w += v.w * v.w;
    }
    int c = threadIdx.x * 4;
    atomicAdd(&g_colsum[c + 0], s.x); atomicAdd(&g_colsum[c + 1], s.y);
    atomicAdd(&g_colsum[c + 2], s.z); atomicAdd(&g_colsum[c + 3], s.w);
    atomicAdd(&g_colsumsq[c + 0], q.x); atomicAdd(&g_colsumsq[c + 1], q.y);
    atomicAdd(&g_colsumsq[c + 2], q.z); atomicAdd(&g_colsumsq[c + 3], q.w);
}
__global__ void k_bncoef(const float* __restrict__ gamma,
                         const float* __restrict__ beta) {
    int c = threadIdx.x;
    if (c < HIDD) {
        float mu  = g_colsum[c]   * (1.0f / NTOT);
        float var = g_colsumsq[c] * (1.0f / NTOT) - mu * mu;
        float s = gamma[c] * rsqrtf(var + EPSB);
        g_sc[c] = s;
        g_sh[c] = beta[c] - mu * s;
    }
}
__global__ void k_bnapply(const float* __restrict__ T,
                          __nv_bfloat16* __restrict__ Yh,
                          __nv_bfloat16* __restrict__ Yl) {
    int idx = blockIdx.x * blockDim.x + threadIdx.x;   // float4 index
    const int TOT4 = NTOT * (HIDD / 4);
    if (idx >= TOT4) return;
    int c4 = idx & (HIDD / 4 - 1);
    float4 v = ((const float4*)T)[idx];
    float4 s = ((const float4*)g_sc)[c4];
    float4 h = ((const float4*)g_sh)[c4];
    float f[4];
    f[0] = fmaxf(fmaf(v.x, s.x, h.x), 0.f);
    f[1] = fmaxf(fmaf(v.y, s.y, h.y), 0.f);
    f[2] = fmaxf(fmaf(v.z, s.z, h.z), 0.f);
    f[3] = fmaxf(fmaf(v.w, s.w, h.w), 0.f);
    __nv_bfloat16 hb[4], lb[4];
#pragma unroll
    for (int j = 0; j < 4; j++) {
        hb[j] = __float2bfloat16(f[j]);
        lb[j] = __float2bfloat16(f[j] - __bfloat162float(hb[j]));
    }
    __nv_bfloat162* hp = (__nv_bfloat162*)Yh + idx * 2;
    __nv_bfloat162* lp = (__nv_bfloat162*)Yl + idx * 2;
    hp[0] = __halves2bfloat162(hb[0], hb[1]);
    hp[1] = __halves2bfloat162(hb[2], hb[3]);
    lp[0] = __halves2bfloat162(lb[0], lb[1]);
    lp[1] = __halves2bfloat162(lb[2], lb[3]);
}

// ---------------------------------------------------------------------------
// Launch
// ---------------------------------------------------------------------------
extern "C" void kernel_launch(void* const* d_in, const int* in_sizes, int n_in,
                              void* d_out, int out_size) {
    const float* x_src = (const float*)d_in[0];
    const float* x_dst = (const float*)d_in[1];
    const float* W_src = (const float*)d_in[2];
    const float* b_src = (const float*)d_in[3];
    const float* W_dst = (const float*)d_in[4];
    const float* b_dst = (const float*)d_in[5];
    const float* W1l   = (const float*)d_in[6];
    const float* b1    = (const float*)d_in[7];
    const float* W1r   = (const float*)d_in[8];
    const float* W2l   = (const float*)d_in[9];
    const float* b2    = (const float*)d_in[10];
    const float* W2r   = (const float*)d_in[11];
    const float* gamma = (const float*)d_in[12];
    const float* beta  = (const float*)d_in[13];
    const void*  ei    = d_in[14];
    float* out = (float*)d_out;

    static int attr_set = 0;
    if (!attr_set) {
        cudaFuncSetAttribute(k_mgemm2, cudaFuncAttributeMaxDynamicSharedMemorySize, TG_SMEM);
        attr_set = 1;
    }

    __nv_bfloat16 *Whp, *Wlp, *xshp, *xslp, *xdhp, *xdlp, *Xhp, *Xlp, *Yhp, *Ylp;
    float *Z1p, *T1p, *Z2p;
    cudaGetSymbolAddress((void**)&Whp,  g_Wh);
    cudaGetSymbolAddress((void**)&Wlp,  g_Wl);
    cudaGetSymbolAddress((void**)&xshp, g_xsh);
    cudaGetSymbolAddress((void**)&xslp, g_xsl);
    cudaGetSymbolAddress((void**)&xdhp, g_xdh);
    cudaGetSymbolAddress((void**)&xdlp, g_xdl);
    cudaGetSymbolAddress((void**)&Xhp,  g_Xh);
    cudaGetSymbolAddress((void**)&Xlp,  g_Xl);
    cudaGetSymbolAddress((void**)&Yhp,  g_Yh);
    cudaGetSymbolAddress((void**)&Ylp,  g_Yl);
    cudaGetSymbolAddress((void**)&Z1p,  g_Z1);
    cudaGetSymbolAddress((void**)&T1p,  g_T1);
    cudaGetSymbolAddress((void**)&Z2p,  g_Z2);

    // ---- fused splits (one launch for all 8 arrays) ----
    SplitJobs sj;
    const float* srcs[8] = {x_src, x_dst, W_src, W_dst, W1l, W1r, W2l, W2r};
    __nv_bfloat16* hs[8] = {xshp, xdhp, Whp + O_WSRC, Whp + O_WDST,
                            Whp + O_W1L, Whp + O_W1R, Whp + O_W2L, Whp + O_W2R};
    __nv_bfloat16* ls[8] = {xslp, xdlp, Wlp + O_WSRC, Wlp + O_WDST,
                            Wlp + O_W1L, Wlp + O_W1R, Wlp + O_W2L, Wlp + O_W2R};
    int ns[8] = {NSRC * INS, NDST * IND, HIDD * INS, HIDD * IND,
                 HIDD * HIDD, HIDD * HIDD, OUTD * HIDD, OUTD * HIDD};
    int total_blk = 0;
    for (int k = 0; k < 8; k++) {
        sj.src[k] = (const float4*)srcs[k];
        sj.h[k] = hs[k]; sj.l[k] = ls[k];
        sj.n4[k] = ns[k] / 4;
        sj.nblk[k] = (sj.n4[k] + 255) / 256;
        total_blk += sj.nblk[k];
    }
    k_split8<<<total_blk, 256>>>(sj);                                   // 1

    // ---- CSR build ----
    k_prep<<<(2 * NEDGE + 255) / 256, 256>>>(ei);                       // 2
    k_hist<<<(NEDGE + 255) / 256, 256>>>();                             // 3
    k_scan<<<1, 1024>>>();                                              // 4
    k_fill<<<(NEDGE + 255) / 256, 256>>>();                             // 5

    auto mkargs = [](const __nv_bfloat16* Ah, const __nv_bfloat16* Al,
                     const __nv_bfloat16* Bh, const __nv_bfloat16* Bl,
                     const float* bias, float* Cf,
                     __nv_bfloat16* Ch, __nv_bfloat16* Cl,
                     int M, int N, int K) {
        GArgs a;
        a.Ah = Ah; a.Al = Al; a.Bh = Bh; a.Bl = Bl; a.bias = bias;
        a.Cf = Cf; a.Ch = Ch; a.Cl = Cl; a.M = M; a.N = N; a.K = K;
        a.nbx = N / 128;
        a.nblk = a.nbx * ((M + 127) / 128);
        return a;
    };

    // ---- stage A: input projections -> X = concat(h_src, h_dst) ----
    GArgs pa = mkargs(xshp, xslp, Whp + O_WSRC, Wlp + O_WSRC, b_src,
                      nullptr, Xhp, Xlp, NSRC, HIDD, INS);
    GArgs pb = mkargs(xdhp, xdlp, Whp + O_WDST, Wlp + O_WDST, b_dst,
                      nullptr, Xhp + (size_t)NSRC * HIDD, Xlp + (size_t)NSRC * HIDD,
                      NDST, HIDD, IND);
    k_mgemm2<<<pa.nblk + pb.nblk, 256, TG_SMEM>>>(pa, pb);              // 6 <- ncu

    // ---- stage B: layer 1 (Z1 = X[:10k]@W1l.T ; T1 = X@W1r.T + b1) ----
    GArgs ba = mkargs(Xhp, Xlp, Whp + O_W1L, Wlp + O_W1L, nullptr,
                      Z1p, nullptr, nullptr, NSRC, HIDD, HIDD);
    GArgs bb = mkargs(Xhp, Xlp, Whp + O_W1R, Wlp + O_W1R, b1,
                      T1p, nullptr, nullptr, NTOT, HIDD, HIDD);
    k_mgemm2<<<ba.nblk + bb.nblk, 256, TG_SMEM>>>(ba, bb);
    k_agg<<<NDST, HIDD / 4>>>(Z1p, T1p + (size_t)NSRC * HIDD);

    // ---- BatchNorm + ReLU -> bf16 split Y ----
    k_bnstats<<<256, HIDD / 4>>>(T1p);
    k_bncoef<<<1, HIDD>>>(gamma, beta);
    k_bnapply<<<(NTOT * (HIDD / 4) + 255) / 256, 256>>>(T1p, Yhp, Ylp);

    // ---- stage C: layer 2 (Z2 = Y[:10k]@W2l.T ; OUT = Y@W2r.T + b2) ----
    GArgs ca = mkargs(Yhp, Ylp, Whp + O_W2L, Wlp + O_W2L, nullptr,
                      Z2p, nullptr, nullptr, NSRC, OUTD, HIDD);
    GArgs cb = mkargs(Yhp, Ylp, Whp + O_W2R, Wlp + O_W2R, b2,
                      out, nullptr, nullptr, NTOT, OUTD, HIDD);
    k_mgemm2<<<ca.nblk + cb.nblk, 256, TG_SMEM>>>(ca, cb);
    k_agg<<<NDST, OUTD / 4>>>(Z2p, out + (size_t)NSRC * OUTD);
}

// round 12
// speedup vs baseline: 2.7786x; 1.0399x over previous
#include <cuda_runtime.h>
#include <cuda_bf16.h>
#include <cstdint>

// Problem constants (fixed shapes per reference)
#define NSRC  10000
#define NDST  10000
#define NTOT  20000
#define INS   512
#define IND   256
#define HIDD  512
#define OUTD  256
#define NEDGE 160000
#define EPSB  1e-5f

// ---------------------------------------------------------------------------
// PTX helpers — sm_80-baseline only (harness compiles via compute_103
// virtual arch: tcgen05/TMEM unavailable).
// ---------------------------------------------------------------------------
#define SWZ64(o) ((o) ^ (((o) >> 3) & 0x30))   // 64B-row swizzle (8x64B atom)

__device__ __forceinline__ uint32_t smem_to_u32(const void* p) {
    uint32_t a;
    asm("{ .reg .u64 t; cvta.to.shared.u64 t, %1; cvt.u32.u64 %0, t; }"
        : "=r"(a) : "l"(p));
    return a;
}

#define CP16(dst, src) \
    asm volatile("cp.async.cg.shared.global [%0], [%1], 16;" \
                 :: "r"(dst), "l"(src) : "memory")
#define CP_COMMIT() asm volatile("cp.async.commit_group;" ::: "memory")
#define CP_WAIT1()  asm volatile("cp.async.wait_group 1;" ::: "memory")
#define CP_WAIT0()  asm volatile("cp.async.wait_group 0;" ::: "memory")

#define LDSM4(r, addr) \
    asm volatile("ldmatrix.sync.aligned.m8n8.x4.shared.b16 {%0,%1,%2,%3}, [%4];" \
                 : "=r"((r)[0]), "=r"((r)[1]), "=r"((r)[2]), "=r"((r)[3]) \
                 : "r"(addr))

#define MMA16816(d, a, b) \
    asm volatile("mma.sync.aligned.m16n8k16.row.col.f32.bf16.bf16.f32 " \
                 "{%0,%1,%2,%3}, {%4,%5,%6,%7}, {%8,%9}, {%0,%1,%2,%3};" \
                 : "+f"((d)[0]), "+f"((d)[1]), "+f"((d)[2]), "+f"((d)[3]) \
                 : "r"((a)[0]), "r"((a)[1]), "r"((a)[2]), "r"((a)[3]), \
                   "r"((b)[0]), "r"((b)[1]))

// ---------------------------------------------------------------------------
// Scratch (static __device__ — no allocations allowed)
// ---------------------------------------------------------------------------
#define O_WSRC 0
#define O_WDST 262144
#define O_W1L  393216
#define O_W1R  655360
#define O_W2L  917504
#define O_W2R  1048576
#define WTOT   1179648

__device__ __align__(16) __nv_bfloat16 g_Wh[WTOT],  g_Wl[WTOT];
__device__ __align__(16) __nv_bfloat16 g_xsh[NSRC * INS], g_xsl[NSRC * INS];
__device__ __align__(16) __nv_bfloat16 g_xdh[NDST * IND], g_xdl[NDST * IND];
__device__ __align__(16) __nv_bfloat16 g_Xh[NTOT * HIDD], g_Xl[NTOT * HIDD];
__device__ __align__(16) __nv_bfloat16 g_Yh[NTOT * HIDD], g_Yl[NTOT * HIDD];
__device__ __align__(16) float g_Z1[NSRC * HIDD];
__device__ __align__(16) float g_T1[NTOT * HIDD];
__device__ __align__(16) float g_Z2[NSRC * OUTD];
__device__ int   g_edges[2 * NEDGE];
__device__ int   g_cnt[NDST];
__device__ int   g_off[NDST];
__device__ int   g_cur[NDST];
__device__ int   g_csr[NEDGE];
__device__ float g_colsum[HIDD];
__device__ float g_colsumsq[HIDD];
__device__ float g_sc[HIDD];
__device__ float g_sh[HIDD];

// ---------------------------------------------------------------------------
// k_prep: edge dtype detect (per-block, warp ballot) + convert + zero buffers
// JAX with x64 disabled silently stores edge_index as int32; handle both.
// ---------------------------------------------------------------------------
__global__ void k_prep(const void* p) {
    __shared__ int s_is64;
    if (threadIdx.x < 32) {
        const int* q = (const int*)p;
        int v = q[threadIdx.x * 2 + 1];
        unsigned m = __ballot_sync(0xffffffff, v != 0);
        if (threadIdx.x == 0) s_is64 = (m == 0);
    }
    __syncthreads();
    int is64 = s_is64;
    int i = blockIdx.x * blockDim.x + threadIdx.x;
    if (i < 2 * NEDGE)
        g_edges[i] = is64 ? (int)((const long long*)p)[i] : ((const int*)p)[i];
    if (i < NDST) g_cnt[i] = 0;
    if (i < HIDD) { g_colsum[i] = 0.f; g_colsumsq[i] = 0.f; }
}

// ---------------------------------------------------------------------------
// Graph preprocessing: histogram -> scan -> CSR fill
// ---------------------------------------------------------------------------
__global__ void k_hist() {
    int i = blockIdx.x * blockDim.x + threadIdx.x;
    if (i < NEDGE) {
        unsigned d = (unsigned)(g_edges[NEDGE + i] - NSRC);
        if (d < NDST) atomicAdd(&g_cnt[d], 1);
    }
}

// Single-block exclusive scan over g_cnt -> g_off/g_cur.
// Local scan + warp shuffle-scan + one 32-entry cross-warp scan (2 barriers).
__global__ void k_scan() {
    const int PER = 10;            // 1024 threads * 10 >= NDST
    int t = threadIdx.x, base = t * PER;
    int v[PER], s = 0;
#pragma unroll
    for (int i = 0; i < PER; i++) {
        int idx = base + i;
        v[i] = (idx < NDST) ? g_cnt[idx] : 0;
    }
#pragma unroll
    for (int i = 0; i < PER; i++) { int x = v[i]; v[i] = s; s += x; }

    int lane = t & 31, wrp = t >> 5;
    int inc = s;
#pragma unroll
    for (int d = 1; d < 32; d <<= 1) {
        int u = __shfl_up_sync(0xffffffffu, inc, d);
        if (lane >= d) inc += u;
    }
    __shared__ int wsum[32];
    if (lane == 31) wsum[wrp] = inc;
    __syncthreads();
    if (wrp == 0) {
        int w = wsum[lane];
#pragma unroll
        for (int d = 1; d < 32; d <<= 1) {
            int u = __shfl_up_sync(0xffffffffu, w, d);
            if (lane >= d) w += u;
        }
        wsum[lane] = w;
    }
    __syncthreads();
    int ex = inc - s + (wrp ? wsum[wrp - 1] : 0);
#pragma unroll
    for (int i = 0; i < PER; i++) {
        int idx = base + i;
        if (idx < NDST) { int o = ex + v[i]; g_off[idx] = o; g_cur[idx] = o; }
    }
}

__global__ void k_fill() {
    int i = blockIdx.x * blockDim.x + threadIdx.x;
    if (i < NEDGE) {
        unsigned d = (unsigned)(g_edges[NEDGE + i] - NSRC);
        unsigned s = (unsigned)g_edges[i];
        if (d < NDST && s < NSRC) {
            int p = atomicAdd(&g_cur[d], 1);
            if (p < NEDGE) g_csr[p] = (int)s;
        }
    }
}

// ---------------------------------------------------------------------------
// Fused fp32 -> bf16 (hi, lo) split over 8 arrays in ONE launch
// ---------------------------------------------------------------------------
struct SplitJobs {
    const float4* src[8];
    __nv_bfloat16* h[8];
    __nv_bfloat16* l[8];
    int n4[8];
    int nblk[8];
};

__global__ void k_split8(SplitJobs j) {
    int b = blockIdx.x;
    int seg = 0;
#pragma unroll
    for (int s = 0; s < 7; s++)
        if (b >= j.nblk[seg]) { b -= j.nblk[seg]; seg++; }
    int i = b * blockDim.x + threadIdx.x;
    if (i >= j.n4[seg]) return;
    float4 v = j.src[seg][i];
    float f[4] = {v.x, v.y, v.z, v.w};
    __nv_bfloat16 hb[4], lb[4];
#pragma unroll
    for (int k = 0; k < 4; k++) {
        hb[k] = __float2bfloat16(f[k]);
        lb[k] = __float2bfloat16(f[k] - __bfloat162float(hb[k]));
    }
    __nv_bfloat162* hp = (__nv_bfloat162*)j.h[seg] + i * 2;
    __nv_bfloat162* lp = (__nv_bfloat162*)j.l[seg] + i * 2;
    hp[0] = __halves2bfloat162(hb[0], hb[1]);
    hp[1] = __halves2bfloat162(hb[2], hb[3]);
    lp[0] = __halves2bfloat162(lb[0], lb[1]);
    lp[1] = __halves2bfloat162(lb[2], lb[3]);
}

// ---------------------------------------------------------------------------
// Warp-MMA bf16-split GEMM body: C[M,N] = (Ah+Al)[M,K] @ (Bh+Bl)[N,K]^T (+bias)
// 128x128 tile, 8 warps (4M x 2N), warp tile 32x64, m16n8k16 HMMA,
// 3 MMAs per term (hi*hi + hi*lo + lo*hi).
// 3-stage cp.async pipeline (32KB/stage = 96KB) -> 2 CTAs/SM.
// ---------------------------------------------------------------------------
#define STG_BYTES 32768
#define TG_SMEM   (3 * STG_BYTES)

__device__ __forceinline__ void mgemm_body(
    const __nv_bfloat16* __restrict__ Ah, const __nv_bfloat16* __restrict__ Al,
    const __nv_bfloat16* __restrict__ Bh, const __nv_bfloat16* __restrict__ Bl,
    const float* __restrict__ bias,
    float* __restrict__ Cf,
    __nv_bfloat16* __restrict__ Ch, __nv_bfloat16* __restrict__ Cl,
    int M, int N, int K, int m0, int n0)
{
    extern __shared__ __align__(1024) char smem[];
    const uint32_t smb = smem_to_u32(smem);
    const int tid = threadIdx.x, wid = tid >> 5, lane = tid & 31;
    const int warp_m = (wid >> 1) * 32;     // 4 warps along M
    const int warp_n = (wid & 1) * 64;      // 2 warps along N

    float acc[2][8][4] = {};

    const int NC = K >> 5;   // K chunks of 32

    // stage layout: Ah @0, Al @8K, Bh @16K, Bl @24K  (64B rows, SW64 swizzle)
    auto load_chunk = [&](int c, int buf) {
        uint32_t bo = smb + (uint32_t)buf * STG_BYTES;
        int k0 = c << 5;
#pragma unroll
        for (int it = 0; it < 2; it++) {
            int seg = tid + it * 256;        // 0..511
            int row = seg >> 2;              // 0..127
            int sg  = seg & 3;               // 16B segment in 64B row
            uint32_t sw = SWZ64((uint32_t)(row * 64 + sg * 16));
            size_t acol = (size_t)(k0 + sg * 8);
            int gm = m0 + row; if (gm >= M) gm = M - 1;   // clamp: never stored
            int gn = n0 + row;
            CP16(bo + sw,         (const char*)(Ah + (size_t)gm * K + acol));
            CP16(bo + 8192  + sw, (const char*)(Al + (size_t)gm * K + acol));
            CP16(bo + 16384 + sw, (const char*)(Bh + (size_t)gn * K + acol));
            CP16(bo + 24576 + sw, (const char*)(Bl + (size_t)gn * K + acol));
        }
        CP_COMMIT();
    };

    load_chunk(0, 0);
    if (NC > 1) load_chunk(1, 1);

    const int q  = lane >> 3;   // ldmatrix sub-matrix index
    const int rr = lane & 7;

    int buf_c = 0;
    for (int c = 0; c < NC; c++) {
        if (c + 1 < NC) CP_WAIT1(); else CP_WAIT0();
        __syncthreads();                        // chunk-c visible; buf of c-1 free
        if (c + 2 < NC) {
            int nb = buf_c + 2; if (nb >= 3) nb -= 3;
            load_chunk(c + 2, nb);
        }

        uint32_t bo = smb + (uint32_t)buf_c * STG_BYTES;
#pragma unroll
        for (int ks = 0; ks < 2; ks++) {
            const uint32_t kb = (uint32_t)(ks * 32 + (q >> 1) * 16);
            uint32_t ahf[2][4], alf[2][4];
#pragma unroll
            for (int mi = 0; mi < 2; mi++) {
                uint32_t arow = (uint32_t)(warp_m + mi * 16 + (q & 1) * 8 + rr);
                uint32_t ad = bo + SWZ64(arow * 64 + kb);
                LDSM4(ahf[mi], ad);
                LDSM4(alf[mi], ad + 8192);
            }
#pragma unroll
            for (int nj = 0; nj < 4; nj++) {
                uint32_t bhf[4], blf[4];
                uint32_t brow = (uint32_t)(warp_n + nj * 16 + (q & 1) * 8 + rr);
                uint32_t bd = bo + 16384 + SWZ64(brow * 64 + kb);
                LDSM4(bhf, bd);
                LDSM4(blf, bd + 8192);
#pragma unroll
                for (int mi = 0; mi < 2; mi++)
#pragma unroll
                    for (int sub = 0; sub < 2; sub++) {
                        const int ni = nj * 2 + sub;
                        uint32_t bh2[2] = { bhf[sub], bhf[sub + 2] };
                        uint32_t bl2[2] = { blf[sub], blf[sub + 2] };
                        MMA16816(acc[mi][ni], ahf[mi], bh2);   // hi*hi
                        MMA16816(acc[mi][ni], ahf[mi], bl2);   // hi*lo
                        MMA16816(acc[mi][ni], alf[mi], bh2);   // lo*hi
                    }
            }
        }
        if (++buf_c == 3) buf_c = 0;
    }

    // --- epilogue ---
#pragma unroll
    for (int mi = 0; mi < 2; mi++) {
        int mrow = m0 + warp_m + mi * 16 + (lane >> 2);
#pragma unroll
        for (int half = 0; half < 2; half++) {
            int gm = mrow + half * 8;
            if (gm < M) {
#pragma unroll
                for (int ni = 0; ni < 8; ni++) {
                    int gn = n0 + warp_n + ni * 8 + (lane & 3) * 2;
                    float v0 = acc[mi][ni][half * 2 + 0];
                    float v1 = acc[mi][ni][half * 2 + 1];
                    if (bias) { v0 += bias[gn]; v1 += bias[gn + 1]; }
                    size_t o = (size_t)gm * N + gn;
                    if (Cf) *(float2*)(Cf + o) = make_float2(v0, v1);
                    if (Ch) {
                        __nv_bfloat16 h0 = __float2bfloat16(v0);
                        __nv_bfloat16 h1 = __float2bfloat16(v1);
                        *(__nv_bfloat162*)(Ch + o) = __halves2bfloat162(h0, h1);
                        *(__nv_bfloat162*)(Cl + o) = __halves2bfloat162(
                            __float2bfloat16(v0 - __bfloat162float(h0)),
                            __float2bfloat16(v1 - __bfloat162float(h1)));
                    }
                }
            }
        }
    }
}

// ---------------------------------------------------------------------------
// Dual-GEMM launch: grid covers two independent GEMMs so the block scheduler
// backfills GEMM0's tail wave with GEMM1's head blocks (kills wave quant).
// ---------------------------------------------------------------------------
struct GArgs {
    const __nv_bfloat16 *Ah, *Al, *Bh, *Bl;
    const float* bias;
    float* Cf;
    __nv_bfloat16 *Ch, *Cl;
    int M, N, K;
    int nblk, nbx;
};

__global__ void __launch_bounds__(256, 2) k_mgemm2(GArgs a0, GArgs a1) {
    int b = blockIdx.x;
    if (b < a0.nblk) {
        int by = b / a0.nbx, bx = b - by * a0.nbx;
        mgemm_body(a0.Ah, a0.Al, a0.Bh, a0.Bl, a0.bias, a0.Cf, a0.Ch, a0.Cl,
                   a0.M, a0.N, a0.K, by * 128, bx * 128);
    } else {
        b -= a0.nblk;
        int by = b / a1.nbx, bx = b - by * a1.nbx;
        mgemm_body(a1.Ah, a1.Al, a1.Bh, a1.Bl, a1.bias, a1.Cf, a1.Ch, a1.Cl,
                   a1.M, a1.N, a1.K, by * 128, bx * 128);
    }
}

// ---------------------------------------------------------------------------
// CSR aggregation: C[d] += mean_{s in nbrs(d)} Z[s]   (2-deep unroll)
// ---------------------------------------------------------------------------
__global__ void k_agg(const float* __restrict__ Z, float* __restrict__ C) {
    int d = blockIdx.x;
    int deg = g_cnt[d];
    if (deg == 0) return;
    int W4 = blockDim.x;
    const float4* Z4 = (const float4*)Z;
    float4 acc = make_float4(0.f, 0.f, 0.f, 0.f);
    int o = g_off[d];
    int e = 0;
    for (; e + 2 <= deg; e += 2) {
        int s0 = g_csr[o + e], s1 = g_csr[o + e + 1];
        float4 v0 = Z4[(size_t)s0 * W4 + threadIdx.x];
        float4 v1 = Z4[(size_t)s1 * W4 + threadIdx.x];
        acc.x += v0.x + v1.x; acc.y += v0.y + v1.y;
        acc.z += v0.z + v1.z; acc.w += v0.w + v1.w;
    }
    if (e < deg) {
        int s = g_csr[o + e];
        float4 v = Z4[(size_t)s * W4 + threadIdx.x];
        acc.x += v.x; acc.y += v.y; acc.z += v.z; acc.w += v.w;
    }
    float inv = 1.0f / (float)deg;
    float4* C4 = (float4*)C;
    size_t oi = (size_t)d * W4 + threadIdx.x;
    float4 c = C4[oi];
    c.x += acc.x * inv; c.y += acc.y * inv;
    c.z += acc.z * inv; c.w += acc.w * inv;
    C4[oi] = c;
}

// ---------------------------------------------------------------------------
// BatchNorm (training stats) + ReLU; apply writes bf16 hi/lo for layer 2
// ---------------------------------------------------------------------------
__global__ void k_bnstats(const float* __restrict__ T) {
    const float4* T4 = (const float4*)T;
    float4 s = make_float4(0.f, 0.f, 0.f, 0.f);
    float4 q = make_float4(0.f, 0.f, 0.f, 0.f);
    for (int r = blockIdx.x; r < NTOT; r += gridDim.x) {
        float4 v = T4[(size_t)r * (HIDD / 4) + threadIdx.x];
        s.x += v.x; s.y += v.y; s.z += v.z; s.w += v.w;
        q.x += v.x * v.x; q.y += v.y * v.y; q.z += v.z * v.z; q.w += v.w * v.w;
    }
    int c = threadIdx.x * 4;
    atomicAdd(&g_colsum[c + 0], s.x); atomicAdd(&g_colsum[c + 1], s.y);
    atomicAdd(&g_colsum[c + 2], s.z); atomicAdd(&g_colsum[c + 3], s.w);
    atomicAdd(&g_colsumsq[c + 0], q.x); atomicAdd(&g_colsumsq[c + 1], q.y);
    atomicAdd(&g_colsumsq[c + 2], q.z); atomicAdd(&g_colsumsq[c + 3], q.w);
}
__global__ void k_bncoef(const float* __restrict__ gamma,
                         const float* __restrict__ beta) {
    int c = threadIdx.x;
    if (c < HIDD) {
        float mu  = g_colsum[c]   * (1.0f / NTOT);
        float var = g_colsumsq[c] * (1.0f / NTOT) - mu * mu;
        float s = gamma[c] * rsqrtf(var + EPSB);
        g_sc[c] = s;
        g_sh[c] = beta[c] - mu * s;
    }
}
__global__ void k_bnapply(const float* __restrict__ T,
                          __nv_bfloat16* __restrict__ Yh,
                          __nv_bfloat16* __restrict__ Yl) {
    int idx = blockIdx.x * blockDim.x + threadIdx.x;   // float4 index
    const int TOT4 = NTOT * (HIDD / 4);
    if (idx >= TOT4) return;
    int c4 = idx & (HIDD / 4 - 1);
    float4 v = ((const float4*)T)[idx];
    float4 s = ((const float4*)g_sc)[c4];
    float4 h = ((const float4*)g_sh)[c4];
    float f[4];
    f[0] = fmaxf(fmaf(v.x, s.x, h.x), 0.f);
    f[1] = fmaxf(fmaf(v.y, s.y, h.y), 0.f);
    f[2] = fmaxf(fmaf(v.z, s.z, h.z), 0.f);
    f[3] = fmaxf(fmaf(v.w, s.w, h.w), 0.f);
    __nv_bfloat16 hb[4], lb[4];
#pragma unroll
    for (int j = 0; j < 4; j++) {
        hb[j] = __float2bfloat16(f[j]);
        lb[j] = __float2bfloat16(f[j] - __bfloat162float(hb[j]));
    }
    __nv_bfloat162* hp = (__nv_bfloat162*)Yh + idx * 2;
    __nv_bfloat162* lp = (__nv_bfloat162*)Yl + idx * 2;
    hp[0] = __halves2bfloat162(hb[0], hb[1]);
    hp[1] = __halves2bfloat162(hb[2], hb[3]);
    lp[0] = __halves2bfloat162(lb[0], lb[1]);
    lp[1] = __halves2bfloat162(lb[2], lb[3]);
}

// ---------------------------------------------------------------------------
// Launch
// ---------------------------------------------------------------------------
extern "C" void kernel_launch(void* const* d_in, const int* in_sizes, int n_in,
                              void* d_out, int out_size) {
    const float* x_src = (const float*)d_in[0];
    const float* x_dst = (const float*)d_in[1];
    const float* W_src = (const float*)d_in[2];
    const float* b_src = (const float*)d_in[3];
    const float* W_dst = (const float*)d_in[4];
    const float* b_dst = (const float*)d_in[5];
    const float* W1l   = (const float*)d_in[6];
    const float* b1    = (const float*)d_in[7];
    const float* W1r   = (const float*)d_in[8];
    const float* W2l   = (const float*)d_in[9];
    const float* b2    = (const float*)d_in[10];
    const float* W2r   = (const float*)d_in[11];
    const float* gamma = (const float*)d_in[12];
    const float* beta  = (const float*)d_in[13];
    const void*  ei    = d_in[14];
    float* out = (float*)d_out;

    static int inited = 0;
    static cudaStream_t s2;
    static cudaEvent_t evF, evJ;
    if (!inited) {
        cudaFuncSetAttribute(k_mgemm2, cudaFuncAttributeMaxDynamicSharedMemorySize, TG_SMEM);
        cudaStreamCreateWithFlags(&s2, cudaStreamNonBlocking);
        cudaEventCreateWithFlags(&evF, cudaEventDisableTiming);
        cudaEventCreateWithFlags(&evJ, cudaEventDisableTiming);
        inited = 1;
    }

    __nv_bfloat16 *Whp, *Wlp, *xshp, *xslp, *xdhp, *xdlp, *Xhp, *Xlp, *Yhp, *Ylp;
    float *Z1p, *T1p, *Z2p;
    cudaGetSymbolAddress((void**)&Whp,  g_Wh);
    cudaGetSymbolAddress((void**)&Wlp,  g_Wl);
    cudaGetSymbolAddress((void**)&xshp, g_xsh);
    cudaGetSymbolAddress((void**)&xslp, g_xsl);
    cudaGetSymbolAddress((void**)&xdhp, g_xdh);
    cudaGetSymbolAddress((void**)&xdlp, g_xdl);
    cudaGetSymbolAddress((void**)&Xhp,  g_Xh);
    cudaGetSymbolAddress((void**)&Xlp,  g_Xl);
    cudaGetSymbolAddress((void**)&Yhp,  g_Yh);
    cudaGetSymbolAddress((void**)&Ylp,  g_Yl);
    cudaGetSymbolAddress((void**)&Z1p,  g_Z1);
    cudaGetSymbolAddress((void**)&T1p,  g_T1);
    cudaGetSymbolAddress((void**)&Z2p,  g_Z2);

    // ---- fork: CSR build runs on side stream, overlapping splits + GEMMs ----
    cudaEventRecord(evF, 0);
    cudaStreamWaitEvent(s2, evF, 0);
    k_prep<<<(2 * NEDGE + 255) / 256, 256, 0, s2>>>(ei);
    k_hist<<<(NEDGE + 255) / 256, 256, 0, s2>>>();
    k_scan<<<1, 1024, 0, s2>>>();
    k_fill<<<(NEDGE + 255) / 256, 256, 0, s2>>>();
    cudaEventRecord(evJ, s2);

    // ---- fused splits (one launch for all 8 arrays) ----
    SplitJobs sj;
    const float* srcs[8] = {x_src, x_dst, W_src, W_dst, W1l, W1r, W2l, W2r};
    __nv_bfloat16* hs[8] = {xshp, xdhp, Whp + O_WSRC, Whp + O_WDST,
                            Whp + O_W1L, Whp + O_W1R, Whp + O_W2L, Whp + O_W2R};
    __nv_bfloat16* ls[8] = {xslp, xdlp, Wlp + O_WSRC, Wlp + O_WDST,
                            Wlp + O_W1L, Wlp + O_W1R, Wlp + O_W2L, Wlp + O_W2R};
    int ns[8] = {NSRC * INS, NDST * IND, HIDD * INS, HIDD * IND,
                 HIDD * HIDD, HIDD * HIDD, OUTD * HIDD, OUTD * HIDD};
    int total_blk = 0;
    for (int k = 0; k < 8; k++) {
        sj.src[k] = (const float4*)srcs[k];
        sj.h[k] = hs[k]; sj.l[k] = ls[k];
        sj.n4[k] = ns[k] / 4;
        sj.nblk[k] = (sj.n4[k] + 255) / 256;
        total_blk += sj.nblk[k];
    }
    k_split8<<<total_blk, 256>>>(sj);

    auto mkargs = [](const __nv_bfloat16* Ah, const __nv_bfloat16* Al,
                     const __nv_bfloat16* Bh, const __nv_bfloat16* Bl,
                     const float* bias, float* Cf,
                     __nv_bfloat16* Ch, __nv_bfloat16* Cl,
                     int M, int N, int K) {
        GArgs a;
        a.Ah = Ah; a.Al = Al; a.Bh = Bh; a.Bl = Bl; a.bias = bias;
        a.Cf = Cf; a.Ch = Ch; a.Cl = Cl; a.M = M; a.N = N; a.K = K;
        a.nbx = N / 128;
        a.nblk = a.nbx * ((M + 127) / 128);
        return a;
    };

    // ---- stage A: input projections -> X = concat(h_src, h_dst) ----
    GArgs pa = mkargs(xshp, xslp, Whp + O_WSRC, Wlp + O_WSRC, b_src,
                      nullptr, Xhp, Xlp, NSRC, HIDD, INS);
    GArgs pb = mkargs(xdhp, xdlp, Whp + O_WDST, Wlp + O_WDST, b_dst,
                      nullptr, Xhp + (size_t)NSRC * HIDD, Xlp + (size_t)NSRC * HIDD,
                      NDST, HIDD, IND);
    k_mgemm2<<<pa.nblk + pb.nblk, 256, TG_SMEM>>>(pa, pb);

    // ---- stage B: layer 1 (Z1 = X[:10k]@W1l.T ; T1 = X@W1r.T + b1) ----
    GArgs ba = mkargs(Xhp, Xlp, Whp + O_W1L, Wlp + O_W1L, nullptr,
                      Z1p, nullptr, nullptr, NSRC, HIDD, HIDD);
    GArgs bb = mkargs(Xhp, Xlp, Whp + O_W1R, Wlp + O_W1R, b1,
                      T1p, nullptr, nullptr, NTOT, HIDD, HIDD);
    k_mgemm2<<<ba.nblk + bb.nblk, 256, TG_SMEM>>>(ba, bb);

    // ---- join: CSR chain must be done before aggregation ----
    cudaStreamWaitEvent(0, evJ, 0);
    k_agg<<<NDST, HIDD / 4>>>(Z1p, T1p + (size_t)NSRC * HIDD);

    // ---- BatchNorm + ReLU -> bf16 split Y ----
    k_bnstats<<<256, HIDD / 4>>>(T1p);
    k_bncoef<<<1, HIDD>>>(gamma, beta);
    k_bnapply<<<(NTOT * (HIDD / 4) + 255) / 256, 256>>>(T1p, Yhp, Ylp);

    // ---- stage C: layer 2 (Z2 = Y[:10k]@W2l.T ; OUT = Y@W2r.T + b2) ----
    GArgs ca = mkargs(Yhp, Ylp, Whp + O_W2L, Wlp + O_W2L, nullptr,
                      Z2p, nullptr, nullptr, NSRC, OUTD, HIDD);
    GArgs cb = mkargs(Yhp, Ylp, Whp + O_W2R, Wlp + O_W2R, b2,
                      out, nullptr, nullptr, NTOT, OUTD, HIDD);
    k_mgemm2<<<ca.nblk + cb.nblk, 256, TG_SMEM>>>(ca, cb);
    k_agg<<<NDST, OUTD / 4>>>(Z2p, out + (size_t)NSRC * OUTD);
}